// round 1
// baseline (speedup 1.0000x reference)
#include <cuda_runtime.h>
#include <cstdint>
#include <cmath>

#define B_  64
#define T_  512
#define E_  512
#define H_  1024
#define M_  (B_*T_)     // 32768 rows
#define G3_ (3*H_)      // 3072

// ---------------- scratch (static device globals; no allocation) ----------------
__device__ float g_act[(size_t)M_ * E_];     // embedding output [M, E]
__device__ float g_xg [(size_t)M_ * G3_];    // per-layer input-gate preactivations [M, 3H]
__device__ float g_buf0[(size_t)M_ * H_];    // layer output ping
__device__ float g_buf1[(size_t)M_ * H_];    // layer output pong
__device__ float g_h[2][B_ * H_];            // recurrent state double buffer
__device__ unsigned g_bar_count = 0;
__device__ unsigned g_bar_gen   = 0;
__device__ int g_x_is_i64 = 1;

// ---------------- int64-vs-int32 detection for x ----------------
__global__ void detect_kernel(const int* __restrict__ x32) {
    __shared__ int nz;
    if (threadIdx.x == 0) nz = 0;
    __syncthreads();
    // If x is int64 (values < 32000), every odd 32-bit word is 0.
    if (x32[2 * threadIdx.x + 1] != 0) atomicExch(&nz, 1);
    __syncthreads();
    if (threadIdx.x == 0) g_x_is_i64 = (nz == 0) ? 1 : 0;
}

// ---------------- embedding gather + pad mask ----------------
__global__ __launch_bounds__(128) void embed_kernel(
    const void* __restrict__ xraw, const float* __restrict__ emb,
    float* __restrict__ mask_out)
{
    const int r = blockIdx.x;                 // row = b*T + t
    long long idx;
    if (g_x_is_i64) idx = ((const long long*)xraw)[r];
    else            idx = (long long)((const int*)xraw)[r];
    const float4* src = (const float4*)(emb + (size_t)idx * E_);
    float4* dst = (float4*)(g_act + (size_t)r * E_);
    dst[threadIdx.x] = src[threadIdx.x];      // 128 threads * float4 = 512 floats
    if (threadIdx.x == 0) mask_out[r] = (idx != 0) ? 1.0f : 0.0f;
}

// ---------------- fp32 tiled GEMM: C[M,3072] = A[M,K] @ W[K,3072] + bias ----------------
__global__ __launch_bounds__(256) void gemm_bias_kernel(
    const float* __restrict__ A, const float* __restrict__ W,
    const float* __restrict__ bias, float* __restrict__ C, int K)
{
    __shared__ float As[16][132];   // A tile, transposed [k][m], padded
    __shared__ float Ws[16][128];   // W tile [k][n]
    const int bn = blockIdx.x, bm = blockIdx.y;
    const int tid = threadIdx.x;
    const int tx = tid & 15, ty = tid >> 4;
    const float* Ab = A + (size_t)bm * 128 * K;
    const float* Wb = W + bn * 128;

    float acc[8][8];
#pragma unroll
    for (int i = 0; i < 8; i++)
#pragma unroll
        for (int j = 0; j < 8; j++) acc[i][j] = 0.0f;

    for (int k0 = 0; k0 < K; k0 += 16) {
#pragma unroll
        for (int l = 0; l < 2; l++) {
            int id = tid + l * 256;
            int r = id >> 2, q = id & 3;
            float4 v = *(const float4*)(Ab + (size_t)r * K + k0 + q * 4);
            As[q*4+0][r] = v.x; As[q*4+1][r] = v.y;
            As[q*4+2][r] = v.z; As[q*4+3][r] = v.w;
        }
#pragma unroll
        for (int l = 0; l < 2; l++) {
            int id = tid + l * 256;
            int r = id >> 5, q = id & 31;
            *(float4*)&Ws[r][q*4] = *(const float4*)(Wb + (size_t)(k0 + r) * G3_ + q * 4);
        }
        __syncthreads();
#pragma unroll
        for (int kk = 0; kk < 16; kk++) {
            float a[8], b[8];
            *(float4*)&a[0] = *(float4*)&As[kk][ty*8];
            *(float4*)&a[4] = *(float4*)&As[kk][ty*8+4];
            *(float4*)&b[0] = *(float4*)&Ws[kk][tx*8];
            *(float4*)&b[4] = *(float4*)&Ws[kk][tx*8+4];
#pragma unroll
            for (int i = 0; i < 8; i++)
#pragma unroll
                for (int j = 0; j < 8; j++)
                    acc[i][j] = fmaf(a[i], b[j], acc[i][j]);
        }
        __syncthreads();
    }
#pragma unroll
    for (int i = 0; i < 8; i++) {
        size_t row = (size_t)bm * 128 + ty * 8 + i;
        float* Crow = C + row * G3_ + bn * 128 + tx * 8;
        const float* brow = bias + bn * 128 + tx * 8;
#pragma unroll
        for (int j = 0; j < 8; j += 4) {
            float4 v;
            v.x = acc[i][j+0] + brow[j+0];
            v.y = acc[i][j+1] + brow[j+1];
            v.z = acc[i][j+2] + brow[j+2];
            v.w = acc[i][j+3] + brow[j+3];
            *(float4*)&Crow[j] = v;
        }
    }
}

// ---------------- persistent GRU scan ----------------
#define SC_CTAS    128
#define SC_THREADS 128
#define SC_WSTRIDE 1028           // padded row stride for sW (bank-conflict free)
#define SC_CHK     128            // K chunk staged in smem
#define SC_SMEM_BYTES ((24*SC_WSTRIDE + 64*132) * 4)

__device__ __forceinline__ void grid_barrier() {
    __syncthreads();
    if (threadIdx.x == 0) {
        __threadfence();
        unsigned gen = atomicAdd(&g_bar_gen, 0u);
        __threadfence();
        if (atomicAdd(&g_bar_count, 1u) == SC_CTAS - 1u) {
            atomicExch(&g_bar_count, 0u);
            __threadfence();
            atomicAdd(&g_bar_gen, 1u);
        } else {
            while (*(volatile unsigned*)&g_bar_gen == gen) __nanosleep(64);
        }
        __threadfence();
    }
    __syncthreads();
}

__device__ __forceinline__ float dot4acc(float4 a, float4 w, float acc) {
    acc = fmaf(a.x, w.x, acc);
    acc = fmaf(a.y, w.y, acc);
    acc = fmaf(a.z, w.z, acc);
    acc = fmaf(a.w, w.w, acc);
    return acc;
}

// CTA c owns hidden units [8c, 8c+8). SMEM holds Wh columns for those units
// (all 3 gates, full K=1024) for the whole 512-step scan.
__global__ __launch_bounds__(SC_THREADS, 1) void scan_kernel(
    const float* __restrict__ xg, const float* __restrict__ Wh,
    const float* __restrict__ bh, float* __restrict__ hout,
    float* __restrict__ state_out)
{
    extern __shared__ float smem[];
    float* sW = smem;                       // [24][SC_WSTRIDE]: col = g*8+u, k in [0,1024)
    float* sh = smem + 24 * SC_WSTRIDE;     // [64][132]: staged h chunk

    const int c   = blockIdx.x;
    const int tid = threadIdx.x;
    const int u   = tid & 7;                // unit within slice
    const int bg  = tid >> 3;               // batch group (4 rows each)
    const int j   = c * 8 + u;              // global hidden unit

    // Load Wh slice into SMEM (once per layer; reused 512 steps)
    for (int col = 0; col < 24; col++) {
        int g = col >> 3, uu = col & 7;
        const float* src = Wh + (size_t)(g * H_) + c * 8 + uu;
        for (int k = tid; k < H_; k += SC_THREADS)
            sW[col * SC_WSTRIDE + k] = src[(size_t)k * G3_];
    }
    // Zero initial hidden state for owned units
    for (int i = tid; i < B_ * 8; i += SC_THREADS) {
        int b = i >> 3, uu = i & 7;
        g_h[0][b * H_ + c * 8 + uu] = 0.0f;
    }
    grid_barrier();

    const float bhr = bh[0 * H_ + j];
    const float bhz = bh[1 * H_ + j];
    const float bhn = bh[2 * H_ + j];

    for (int t = 0; t < T_; t++) {
        const float* hprev = g_h[t & 1];
        float*       hnext = g_h[(t + 1) & 1];

        float acc[4][3];
#pragma unroll
        for (int bi = 0; bi < 4; bi++) { acc[bi][0]=0.f; acc[bi][1]=0.f; acc[bi][2]=0.f; }

        for (int k0 = 0; k0 < H_; k0 += SC_CHK) {
            // stage h[:, k0:k0+128] into smem (coalesced)
            for (int i = tid; i < B_ * (SC_CHK / 4); i += SC_THREADS) {
                int b = i >> 5, kq = i & 31;
                *(float4*)&sh[b * 132 + kq * 4] =
                    *(const float4*)&hprev[b * H_ + k0 + kq * 4];
            }
            __syncthreads();
#pragma unroll 4
            for (int kk = 0; kk < SC_CHK; kk += 4) {
                const float4 w0 = *(const float4*)&sW[(0*8 + u) * SC_WSTRIDE + k0 + kk];
                const float4 w1 = *(const float4*)&sW[(1*8 + u) * SC_WSTRIDE + k0 + kk];
                const float4 w2 = *(const float4*)&sW[(2*8 + u) * SC_WSTRIDE + k0 + kk];
#pragma unroll
                for (int bi = 0; bi < 4; bi++) {
                    const float4 a = *(const float4*)&sh[(bg * 4 + bi) * 132 + kk];
                    acc[bi][0] = dot4acc(a, w0, acc[bi][0]);
                    acc[bi][1] = dot4acc(a, w1, acc[bi][1]);
                    acc[bi][2] = dot4acc(a, w2, acc[bi][2]);
                }
            }
            __syncthreads();
        }

#pragma unroll
        for (int bi = 0; bi < 4; bi++) {
            int b = bg * 4 + bi;
            size_t row = (size_t)b * T_ + t;
            const float* xgr = xg + row * G3_;
            float xr = xgr[j], xz = xgr[H_ + j], xn = xgr[2 * H_ + j];
            float rr = 1.0f / (1.0f + expf(-(xr + acc[bi][0] + bhr)));
            float zz = 1.0f / (1.0f + expf(-(xz + acc[bi][1] + bhz)));
            float nn = tanhf(xn + rr * (acc[bi][2] + bhn));
            float hold = hprev[b * H_ + j];
            float hnew = (1.0f - zz) * nn + zz * hold;
            hnext[b * H_ + j] = hnew;
            hout[row * H_ + j] = hnew;
            if (t == T_ - 1) state_out[b * H_ + j] = hnew;
        }
        grid_barrier();
    }
}

// ---------------- launch ----------------
extern "C" void kernel_launch(void* const* d_in, const int* in_sizes, int n_in,
                              void* d_out, int out_size)
{
    const void*  x   = d_in[0];
    const float* emb = (const float*)d_in[1];
    const float* Wx0 = (const float*)d_in[2];
    const float* Wh0 = (const float*)d_in[3];
    const float* bx0 = (const float*)d_in[4];
    const float* bh0 = (const float*)d_in[5];
    const float* Wx  = (const float*)d_in[6];
    const float* Wh  = (const float*)d_in[7];
    const float* bx  = (const float*)d_in[8];
    const float* bh  = (const float*)d_in[9];

    float* out     = (float*)d_out;
    float* enc_out = out;                                  // [B,T,H]
    float* states  = out + (size_t)M_ * H_;                // [4,B,H]
    float* mask    = states + (size_t)4 * B_ * H_;         // [B,T]

    void *p_act, *p_xg, *p_b0, *p_b1;
    cudaGetSymbolAddress(&p_act, g_act);
    cudaGetSymbolAddress(&p_xg,  g_xg);
    cudaGetSymbolAddress(&p_b0,  g_buf0);
    cudaGetSymbolAddress(&p_b1,  g_buf1);
    float* act = (float*)p_act;
    float* xg  = (float*)p_xg;
    float* b0  = (float*)p_b0;
    float* b1  = (float*)p_b1;

    cudaFuncSetAttribute(scan_kernel, cudaFuncAttributeMaxDynamicSharedMemorySize,
                         SC_SMEM_BYTES);

    detect_kernel<<<1, 64>>>((const int*)x);
    embed_kernel<<<M_, 128>>>(x, emb, mask);

    // layer 0: E -> H
    gemm_bias_kernel<<<dim3(G3_ / 128, M_ / 128), 256>>>(act, Wx0, bx0, xg, E_);
    scan_kernel<<<SC_CTAS, SC_THREADS, SC_SMEM_BYTES>>>(xg, Wh0, bh0, b0, states);

    // layers 1..3: H -> H
    for (int l = 0; l < 3; l++) {
        const float* in_act = (l == 1) ? b1 : b0;
        float* out_act      = (l == 2) ? enc_out : ((l == 0) ? b1 : b0);
        gemm_bias_kernel<<<dim3(G3_ / 128, M_ / 128), 256>>>(
            in_act, Wx + (size_t)l * H_ * G3_, bx + (size_t)l * G3_, xg, H_);
        scan_kernel<<<SC_CTAS, SC_THREADS, SC_SMEM_BYTES>>>(
            xg, Wh + (size_t)l * H_ * G3_, bh + (size_t)l * G3_,
            out_act, states + (size_t)(l + 1) * B_ * H_);
    }
}

// round 2
// speedup vs baseline: 1.0622x; 1.0622x over previous
#include <cuda_runtime.h>
#include <cstdint>
#include <cmath>

#define B_  64
#define T_  512
#define E_  512
#define H_  1024
#define M_  (B_*T_)     // 32768 rows
#define G3_ (3*H_)      // 3072

// ---------------- scratch (static device globals; no allocation) ----------------
__device__ float g_act[(size_t)M_ * E_];     // embedding output [M, E]
__device__ float g_xg [(size_t)M_ * G3_];    // per-layer input-gate preactivations [M, 3H]
__device__ float g_buf0[(size_t)M_ * H_];    // layer output ping
__device__ float g_buf1[(size_t)M_ * H_];    // layer output pong
__device__ float g_h[2][B_ * H_];            // recurrent state double buffer
__device__ unsigned g_bar_count = 0;
__device__ unsigned g_bar_gen   = 0;
__device__ int g_x_is_i64 = 1;

// ---------------- packed f32x2 FMA (SASS FFMA2): 2x fp32 FLOP/instr ----------------
union F2U64 { float2 f2; unsigned long long u; };
__device__ __forceinline__ float2 ffma2(float2 a, float2 b, float2 c) {
    F2U64 A, Bv, C, D;
    A.f2 = a; Bv.f2 = b; C.f2 = c;
    asm("fma.rn.f32x2 %0, %1, %2, %3;" : "=l"(D.u) : "l"(A.u), "l"(Bv.u), "l"(C.u));
    return D.f2;
}

__device__ __forceinline__ float fast_tanh(float x) {
    float y;
    asm("tanh.approx.f32 %0, %1;" : "=f"(y) : "f"(x));
    return y;
}
__device__ __forceinline__ float fast_sigmoid(float x) {
    return 0.5f * fast_tanh(0.5f * x) + 0.5f;
}

// ---------------- int64-vs-int32 detection for x ----------------
__global__ void detect_kernel(const int* __restrict__ x32) {
    __shared__ int nz;
    if (threadIdx.x == 0) nz = 0;
    __syncthreads();
    if (x32[2 * threadIdx.x + 1] != 0) atomicExch(&nz, 1);
    __syncthreads();
    if (threadIdx.x == 0) g_x_is_i64 = (nz == 0) ? 1 : 0;
}

// ---------------- embedding gather + pad mask ----------------
__global__ __launch_bounds__(128) void embed_kernel(
    const void* __restrict__ xraw, const float* __restrict__ emb,
    float* __restrict__ mask_out)
{
    const int r = blockIdx.x;                 // row = b*T + t
    long long idx;
    if (g_x_is_i64) idx = ((const long long*)xraw)[r];
    else            idx = (long long)((const int*)xraw)[r];
    const float4* src = (const float4*)(emb + (size_t)idx * E_);
    float4* dst = (float4*)(g_act + (size_t)r * E_);
    dst[threadIdx.x] = src[threadIdx.x];
    if (threadIdx.x == 0) mask_out[r] = (idx != 0) ? 1.0f : 0.0f;
}

// ---------------- fp32x2 tiled GEMM: C[M,3072] = A[M,K] @ W[K,3072] + bias -------
// 128x128 tile, 256 threads, 8x8 per thread (as 8x4 float2 pairs), register-
// prefetched single-buffer K pipeline.
__global__ __launch_bounds__(256) void gemm_bias_kernel(
    const float* __restrict__ A, const float* __restrict__ W,
    const float* __restrict__ bias, float* __restrict__ C, int K)
{
    __shared__ float As[16][132];   // A tile transposed [k][m], padded
    __shared__ float Ws[16][128];   // W tile [k][n]
    const int bn = blockIdx.x, bm = blockIdx.y;
    const int tid = threadIdx.x;
    const int tx = tid & 15, ty = tid >> 4;
    const float* Ab = A + (size_t)bm * 128 * K;
    const float* Wb = W + bn * 128;

    float2 acc[8][4];
#pragma unroll
    for (int i = 0; i < 8; i++)
#pragma unroll
        for (int j = 0; j < 4; j++) acc[i][j] = make_float2(0.f, 0.f);

    float4 ra[2], rw[2];
    // indices for staging
    const int ar = (tid) >> 2, aq = tid & 3;          // l=0
    const int ar1 = (tid + 256) >> 2, aq1 = (tid + 256) & 3;
    const int wr = tid >> 5, wq = tid & 31;           // l=0
    const int wr1 = (tid + 256) >> 5, wq1 = (tid + 256) & 31;

    auto ld = [&](int k0) {
        ra[0] = *(const float4*)(Ab + (size_t)ar  * K + k0 + aq  * 4);
        ra[1] = *(const float4*)(Ab + (size_t)ar1 * K + k0 + aq1 * 4);
        rw[0] = *(const float4*)(Wb + (size_t)(k0 + wr ) * G3_ + wq  * 4);
        rw[1] = *(const float4*)(Wb + (size_t)(k0 + wr1) * G3_ + wq1 * 4);
    };
    auto st = [&]() {
        As[aq *4+0][ar ] = ra[0].x; As[aq *4+1][ar ] = ra[0].y;
        As[aq *4+2][ar ] = ra[0].z; As[aq *4+3][ar ] = ra[0].w;
        As[aq1*4+0][ar1] = ra[1].x; As[aq1*4+1][ar1] = ra[1].y;
        As[aq1*4+2][ar1] = ra[1].z; As[aq1*4+3][ar1] = ra[1].w;
        *(float4*)&Ws[wr ][wq  * 4] = rw[0];
        *(float4*)&Ws[wr1][wq1 * 4] = rw[1];
    };

    ld(0); st(); __syncthreads();
    const int nch = K / 16;
    for (int c = 0; c < nch; c++) {
        if (c + 1 < nch) ld((c + 1) * 16);   // prefetch next chunk into regs
#pragma unroll
        for (int kk = 0; kk < 16; kk++) {
            float a[8];
            *(float4*)&a[0] = *(float4*)&As[kk][ty * 8];
            *(float4*)&a[4] = *(float4*)&As[kk][ty * 8 + 4];
            float2 b2[4];
            *(float4*)&b2[0] = *(float4*)&Ws[kk][tx * 8];
            *(float4*)&b2[2] = *(float4*)&Ws[kk][tx * 8 + 4];
#pragma unroll
            for (int i = 0; i < 8; i++) {
                float2 ai = make_float2(a[i], a[i]);
#pragma unroll
                for (int j = 0; j < 4; j++)
                    acc[i][j] = ffma2(ai, b2[j], acc[i][j]);
            }
        }
        __syncthreads();
        if (c + 1 < nch) { st(); __syncthreads(); }
    }

    float2 bb[4];
    *(float4*)&bb[0] = *(const float4*)(bias + bn * 128 + tx * 8);
    *(float4*)&bb[2] = *(const float4*)(bias + bn * 128 + tx * 8 + 4);
#pragma unroll
    for (int i = 0; i < 8; i++) {
        size_t row = (size_t)bm * 128 + ty * 8 + i;
        float* Crow = C + row * G3_ + bn * 128 + tx * 8;
        float4 v0, v1;
        v0.x = acc[i][0].x + bb[0].x; v0.y = acc[i][0].y + bb[0].y;
        v0.z = acc[i][1].x + bb[1].x; v0.w = acc[i][1].y + bb[1].y;
        v1.x = acc[i][2].x + bb[2].x; v1.y = acc[i][2].y + bb[2].y;
        v1.z = acc[i][3].x + bb[3].x; v1.w = acc[i][3].y + bb[3].y;
        *(float4*)&Crow[0] = v0;
        *(float4*)&Crow[4] = v1;
    }
}

// ---------------- persistent GRU scan ----------------
#define SC_CTAS    128
#define SC_THREADS 256
#define SC_WSTRIDE 1028           // padded row stride for sW
#define SC_CHK     128            // K chunk staged in smem
#define SC_SMEM_BYTES ((24*SC_WSTRIDE + 64*132) * 4)

__device__ __forceinline__ void grid_barrier() {
    __syncthreads();
    if (threadIdx.x == 0) {
        __threadfence();
        unsigned gen = atomicAdd(&g_bar_gen, 0u);
        __threadfence();
        if (atomicAdd(&g_bar_count, 1u) == SC_CTAS - 1u) {
            atomicExch(&g_bar_count, 0u);
            __threadfence();
            atomicAdd(&g_bar_gen, 1u);
        } else {
            while (*(volatile unsigned*)&g_bar_gen == gen) __nanosleep(32);
        }
        __threadfence();
    }
    __syncthreads();
}

// CTA c owns hidden units [8c, 8c+8). SMEM holds Wh columns for those units
// (all 3 gates, full K=1024) for the whole 512-step scan.
// 256 threads: u = tid&7 (unit), bg = tid>>3 (2 batch rows each).
__global__ __launch_bounds__(SC_THREADS, 1) void scan_kernel(
    const float* __restrict__ xg, const float* __restrict__ Wh,
    const float* __restrict__ bh, float* __restrict__ hout,
    float* __restrict__ state_out)
{
    extern __shared__ float smem[];
    float* sW = smem;                       // [24][SC_WSTRIDE]
    float* sh = smem + 24 * SC_WSTRIDE;     // [64][132]

    const int c   = blockIdx.x;
    const int tid = threadIdx.x;
    const int u   = tid & 7;
    const int bg  = tid >> 3;               // 0..31, each owns 2 batch rows
    const int j   = c * 8 + u;

    // Load Wh slice into SMEM (once per layer; reused 512 steps)
    for (int col = 0; col < 24; col++) {
        int g = col >> 3, uu = col & 7;
        const float* src = Wh + (size_t)(g * H_) + c * 8 + uu;
        for (int k = tid; k < H_; k += SC_THREADS)
            sW[col * SC_WSTRIDE + k] = src[(size_t)k * G3_];
    }
    for (int i = tid; i < B_ * 8; i += SC_THREADS) {
        int b = i >> 3, uu = i & 7;
        g_h[0][b * H_ + c * 8 + uu] = 0.0f;
    }
    grid_barrier();

    const float bhr = bh[0 * H_ + j];
    const float bhz = bh[1 * H_ + j];
    const float bhn = bh[2 * H_ + j];

    const float* wr0 = &sW[(0 * 8 + u) * SC_WSTRIDE];
    const float* wr1 = &sW[(1 * 8 + u) * SC_WSTRIDE];
    const float* wr2 = &sW[(2 * 8 + u) * SC_WSTRIDE];

    for (int t = 0; t < T_; t++) {
        const float* hprev = g_h[t & 1];
        float*       hnext = g_h[(t + 1) & 1];

        // prefetch this step's xg and h_old early (consumed after ~12K cycles)
        float xr[2], xz[2], xn[2], hold[2];
#pragma unroll
        for (int bi = 0; bi < 2; bi++) {
            int b = bg * 2 + bi;
            size_t row = (size_t)b * T_ + t;
            const float* xgr = xg + row * G3_;
            xr[bi]   = __ldg(xgr + j);
            xz[bi]   = __ldg(xgr + H_ + j);
            xn[bi]   = __ldg(xgr + 2 * H_ + j);
            hold[bi] = __ldg(hprev + b * H_ + j);
        }

        float2 acc[2][3];
#pragma unroll
        for (int bi = 0; bi < 2; bi++)
#pragma unroll
            for (int g = 0; g < 3; g++) acc[bi][g] = make_float2(0.f, 0.f);

        for (int k0 = 0; k0 < H_; k0 += SC_CHK) {
            // stage h[:, k0:k0+128] into smem (coalesced)
            for (int i = tid; i < B_ * (SC_CHK / 4); i += SC_THREADS) {
                int b = i >> 5, kq = i & 31;
                *(float4*)&sh[b * 132 + kq * 4] =
                    *(const float4*)&hprev[b * H_ + k0 + kq * 4];
            }
            __syncthreads();
#pragma unroll 4
            for (int kk = 0; kk < SC_CHK; kk += 4) {
                const float4 w0 = *(const float4*)&wr0[k0 + kk];
                const float4 w1 = *(const float4*)&wr1[k0 + kk];
                const float4 w2 = *(const float4*)&wr2[k0 + kk];
                const float2 w0l = make_float2(w0.x, w0.y), w0h = make_float2(w0.z, w0.w);
                const float2 w1l = make_float2(w1.x, w1.y), w1h = make_float2(w1.z, w1.w);
                const float2 w2l = make_float2(w2.x, w2.y), w2h = make_float2(w2.z, w2.w);
#pragma unroll
                for (int bi = 0; bi < 2; bi++) {
                    const float4 a = *(const float4*)&sh[(bg * 2 + bi) * 132 + kk];
                    const float2 al = make_float2(a.x, a.y), ah = make_float2(a.z, a.w);
                    acc[bi][0] = ffma2(al, w0l, acc[bi][0]);
                    acc[bi][0] = ffma2(ah, w0h, acc[bi][0]);
                    acc[bi][1] = ffma2(al, w1l, acc[bi][1]);
                    acc[bi][1] = ffma2(ah, w1h, acc[bi][1]);
                    acc[bi][2] = ffma2(al, w2l, acc[bi][2]);
                    acc[bi][2] = ffma2(ah, w2h, acc[bi][2]);
                }
            }
            __syncthreads();
        }

#pragma unroll
        for (int bi = 0; bi < 2; bi++) {
            int b = bg * 2 + bi;
            size_t row = (size_t)b * T_ + t;
            float gr = acc[bi][0].x + acc[bi][0].y;
            float gz = acc[bi][1].x + acc[bi][1].y;
            float gn = acc[bi][2].x + acc[bi][2].y;
            float rr = fast_sigmoid(xr[bi] + gr + bhr);
            float zz = fast_sigmoid(xz[bi] + gz + bhz);
            float nn = fast_tanh(xn[bi] + rr * (gn + bhn));
            float hnew = (1.0f - zz) * nn + zz * hold[bi];
            hnext[b * H_ + j] = hnew;
            hout[row * H_ + j] = hnew;
            if (t == T_ - 1) state_out[b * H_ + j] = hnew;
        }
        grid_barrier();
    }
}

// ---------------- launch ----------------
extern "C" void kernel_launch(void* const* d_in, const int* in_sizes, int n_in,
                              void* d_out, int out_size)
{
    const void*  x   = d_in[0];
    const float* emb = (const float*)d_in[1];
    const float* Wx0 = (const float*)d_in[2];
    const float* Wh0 = (const float*)d_in[3];
    const float* bx0 = (const float*)d_in[4];
    const float* bh0 = (const float*)d_in[5];
    const float* Wx  = (const float*)d_in[6];
    const float* Wh  = (const float*)d_in[7];
    const float* bx  = (const float*)d_in[8];
    const float* bh  = (const float*)d_in[9];

    float* out     = (float*)d_out;
    float* enc_out = out;                                  // [B,T,H]
    float* states  = out + (size_t)M_ * H_;                // [4,B,H]
    float* mask    = states + (size_t)4 * B_ * H_;         // [B,T]

    void *p_act, *p_xg, *p_b0, *p_b1;
    cudaGetSymbolAddress(&p_act, g_act);
    cudaGetSymbolAddress(&p_xg,  g_xg);
    cudaGetSymbolAddress(&p_b0,  g_buf0);
    cudaGetSymbolAddress(&p_b1,  g_buf1);
    float* act = (float*)p_act;
    float* xg  = (float*)p_xg;
    float* b0  = (float*)p_b0;
    float* b1  = (float*)p_b1;

    cudaFuncSetAttribute(scan_kernel, cudaFuncAttributeMaxDynamicSharedMemorySize,
                         SC_SMEM_BYTES);

    detect_kernel<<<1, 64>>>((const int*)x);
    embed_kernel<<<M_, 128>>>(x, emb, mask);

    // layer 0: E -> H
    gemm_bias_kernel<<<dim3(G3_ / 128, M_ / 128), 256>>>(act, Wx0, bx0, xg, E_);
    scan_kernel<<<SC_CTAS, SC_THREADS, SC_SMEM_BYTES>>>(xg, Wh0, bh0, b0, states);

    // layers 1..3: H -> H
    for (int l = 0; l < 3; l++) {
        const float* in_act = (l == 1) ? b1 : b0;
        float* out_act      = (l == 2) ? enc_out : ((l == 0) ? b1 : b0);
        gemm_bias_kernel<<<dim3(G3_ / 128, M_ / 128), 256>>>(
            in_act, Wx + (size_t)l * H_ * G3_, bx + (size_t)l * G3_, xg, H_);
        scan_kernel<<<SC_CTAS, SC_THREADS, SC_SMEM_BYTES>>>(
            xg, Wh + (size_t)l * H_ * G3_, bh + (size_t)l * G3_,
            out_act, states + (size_t)(l + 1) * B_ * H_);
    }
}

// round 3
// speedup vs baseline: 1.4816x; 1.3948x over previous
#include <cuda_runtime.h>
#include <cstdint>
#include <cmath>

#define B_  64
#define T_  512
#define E_  512
#define H_  1024
#define M_  (B_*T_)     // 32768 rows
#define G3_ (3*H_)      // 3072

// ---------------- scratch (static device globals; no allocation) ----------------
__device__ float g_act[(size_t)M_ * E_];     // embedding output [M, E]
__device__ float g_xg [(size_t)M_ * G3_];    // per-layer input-gate preactivations [M, 3H]
__device__ float g_buf0[(size_t)M_ * H_];    // layer output ping
__device__ float g_buf1[(size_t)M_ * H_];    // layer output pong
__device__ float g_h[2][B_ * H_];            // recurrent state double buffer
__device__ unsigned g_grp_cnt[8];
__device__ unsigned g_root_cnt = 0;
__device__ unsigned g_bar_gen  = 0;
__device__ int g_x_is_i64 = 1;

// ---------------- packed f32x2 FMA (SASS FFMA2) ----------------
union F2U64 { float2 f2; unsigned long long u; };
__device__ __forceinline__ float2 ffma2(float2 a, float2 b, float2 c) {
    F2U64 A, Bv, C, D;
    A.f2 = a; Bv.f2 = b; C.f2 = c;
    asm("fma.rn.f32x2 %0, %1, %2, %3;" : "=l"(D.u) : "l"(A.u), "l"(Bv.u), "l"(C.u));
    return D.f2;
}
__device__ __forceinline__ float fast_tanh(float x) {
    float y; asm("tanh.approx.f32 %0, %1;" : "=f"(y) : "f"(x)); return y;
}
__device__ __forceinline__ float fast_sigmoid(float x) {
    return 0.5f * fast_tanh(0.5f * x) + 0.5f;
}

// ---------------- int64-vs-int32 detection for x ----------------
__global__ void detect_kernel(const int* __restrict__ x32) {
    __shared__ int nz;
    if (threadIdx.x == 0) nz = 0;
    __syncthreads();
    if (x32[2 * threadIdx.x + 1] != 0) atomicExch(&nz, 1);
    __syncthreads();
    if (threadIdx.x == 0) g_x_is_i64 = (nz == 0) ? 1 : 0;
}

// ---------------- embedding gather + pad mask ----------------
__global__ __launch_bounds__(128) void embed_kernel(
    const void* __restrict__ xraw, const float* __restrict__ emb,
    float* __restrict__ mask_out)
{
    const int r = blockIdx.x;
    long long idx;
    if (g_x_is_i64) idx = ((const long long*)xraw)[r];
    else            idx = (long long)((const int*)xraw)[r];
    const float4* src = (const float4*)(emb + (size_t)idx * E_);
    float4* dst = (float4*)(g_act + (size_t)r * E_);
    dst[threadIdx.x] = src[threadIdx.x];
    if (threadIdx.x == 0) mask_out[r] = (idx != 0) ? 1.0f : 0.0f;
}

// ---------------- fp32x2 tiled GEMM (unchanged from R2) ----------------
__global__ __launch_bounds__(256) void gemm_bias_kernel(
    const float* __restrict__ A, const float* __restrict__ W,
    const float* __restrict__ bias, float* __restrict__ C, int K)
{
    __shared__ float As[16][132];
    __shared__ float Ws[16][128];
    const int bn = blockIdx.x, bm = blockIdx.y;
    const int tid = threadIdx.x;
    const int tx = tid & 15, ty = tid >> 4;
    const float* Ab = A + (size_t)bm * 128 * K;
    const float* Wb = W + bn * 128;

    float2 acc[8][4];
#pragma unroll
    for (int i = 0; i < 8; i++)
#pragma unroll
        for (int j = 0; j < 4; j++) acc[i][j] = make_float2(0.f, 0.f);

    float4 ra[2], rw[2];
    const int ar = tid >> 2, aq = tid & 3;
    const int ar1 = (tid + 256) >> 2, aq1 = (tid + 256) & 3;
    const int wr = tid >> 5, wq = tid & 31;
    const int wr1 = (tid + 256) >> 5, wq1 = (tid + 256) & 31;

    auto ld = [&](int k0) {
        ra[0] = *(const float4*)(Ab + (size_t)ar  * K + k0 + aq  * 4);
        ra[1] = *(const float4*)(Ab + (size_t)ar1 * K + k0 + aq1 * 4);
        rw[0] = *(const float4*)(Wb + (size_t)(k0 + wr ) * G3_ + wq  * 4);
        rw[1] = *(const float4*)(Wb + (size_t)(k0 + wr1) * G3_ + wq1 * 4);
    };
    auto st = [&]() {
        As[aq *4+0][ar ] = ra[0].x; As[aq *4+1][ar ] = ra[0].y;
        As[aq *4+2][ar ] = ra[0].z; As[aq *4+3][ar ] = ra[0].w;
        As[aq1*4+0][ar1] = ra[1].x; As[aq1*4+1][ar1] = ra[1].y;
        As[aq1*4+2][ar1] = ra[1].z; As[aq1*4+3][ar1] = ra[1].w;
        *(float4*)&Ws[wr ][wq  * 4] = rw[0];
        *(float4*)&Ws[wr1][wq1 * 4] = rw[1];
    };

    ld(0); st(); __syncthreads();
    const int nch = K / 16;
    for (int c = 0; c < nch; c++) {
        if (c + 1 < nch) ld((c + 1) * 16);
#pragma unroll
        for (int kk = 0; kk < 16; kk++) {
            float a[8];
            *(float4*)&a[0] = *(float4*)&As[kk][ty * 8];
            *(float4*)&a[4] = *(float4*)&As[kk][ty * 8 + 4];
            float2 b2[4];
            *(float4*)&b2[0] = *(float4*)&Ws[kk][tx * 8];
            *(float4*)&b2[2] = *(float4*)&Ws[kk][tx * 8 + 4];
#pragma unroll
            for (int i = 0; i < 8; i++) {
                float2 ai = make_float2(a[i], a[i]);
#pragma unroll
                for (int j = 0; j < 4; j++)
                    acc[i][j] = ffma2(ai, b2[j], acc[i][j]);
            }
        }
        __syncthreads();
        if (c + 1 < nch) { st(); __syncthreads(); }
    }

    float2 bb[4];
    *(float4*)&bb[0] = *(const float4*)(bias + bn * 128 + tx * 8);
    *(float4*)&bb[2] = *(const float4*)(bias + bn * 128 + tx * 8 + 4);
#pragma unroll
    for (int i = 0; i < 8; i++) {
        size_t row = (size_t)bm * 128 + ty * 8 + i;
        float* Crow = C + row * G3_ + bn * 128 + tx * 8;
        float4 v0, v1;
        v0.x = acc[i][0].x + bb[0].x; v0.y = acc[i][0].y + bb[0].y;
        v0.z = acc[i][1].x + bb[1].x; v0.w = acc[i][1].y + bb[1].y;
        v1.x = acc[i][2].x + bb[2].x; v1.y = acc[i][2].y + bb[2].y;
        v1.z = acc[i][3].x + bb[3].x; v1.w = acc[i][3].y + bb[3].y;
        *(float4*)&Crow[0] = v0;
        *(float4*)&Crow[4] = v1;
    }
}

// ---------------- persistent GRU scan (register-resident weights) ----------------
#define SC_CTAS    128
#define SC_THREADS 256

// smem layout (floats)
#define SA_ACT   0                          // [2][8][1024] staged h chunks
#define SA_PART  (SA_ACT + 2*8*1024)        // [8][8][3] x 17-padded partials
#define SA_XG    (SA_PART + 64*3*17)        // [64][3][8]
#define SA_HOLD  (SA_XG + 64*3*8)           // [64][8]
#define SA_BH    (SA_HOLD + 64*8)           // [3][8]
#define SC_SMEM_FLOATS (SA_BH + 24)
#define SC_SMEM_BYTES  (SC_SMEM_FLOATS * 4)

__device__ __forceinline__ void cp_async16(uint32_t smem_addr, const void* gptr) {
    asm volatile("cp.async.cg.shared.global [%0], [%1], 16;"
                 :: "r"(smem_addr), "l"(gptr));
}
__device__ __forceinline__ void cp_commit() {
    asm volatile("cp.async.commit_group;");
}
__device__ __forceinline__ void cp_wait0() {
    asm volatile("cp.async.wait_group 0;");
}

// two-level grid barrier: 8 groups of 16 CTAs
__device__ __forceinline__ void grid_barrier(int c) {
    __syncthreads();
    if (threadIdx.x == 0) {
        __threadfence();
        unsigned gen = *(volatile unsigned*)&g_bar_gen;
        int grp = c & 7;
        if (atomicAdd(&g_grp_cnt[grp], 1u) == 15u) {
            if (atomicAdd(&g_root_cnt, 1u) == 7u) {
                atomicExch(&g_root_cnt, 0u);
#pragma unroll
                for (int i = 0; i < 8; i++) atomicExch(&g_grp_cnt[i], 0u);
                __threadfence();
                atomicAdd(&g_bar_gen, 1u);
            }
        }
        while (*(volatile unsigned*)&g_bar_gen == gen) __nanosleep(32);
        __threadfence();
    }
    __syncthreads();
}

// CTA c owns units j in [8c, 8c+8). thread = (u = tid&7, kg = tid>>3).
// Thread holds Wh[k in kg*32..kg*32+32][3 gates][j=8c+u] in REGISTERS.
__global__ __launch_bounds__(SC_THREADS, 1) void scan_kernel(
    const float* __restrict__ xg, const float* __restrict__ Wh,
    const float* __restrict__ bh, float* __restrict__ hout,
    float* __restrict__ state_out)
{
    extern __shared__ float smem[];
    float* sAct  = smem + SA_ACT;
    float* sPart = smem + SA_PART;
    float* sXg   = smem + SA_XG;
    float* sHold = smem + SA_HOLD;
    float* sBh   = smem + SA_BH;

    const int c   = blockIdx.x;
    const int tid = threadIdx.x;
    const int u   = tid & 7;
    const int kg  = tid >> 3;          // 0..31
    const int jbase = c * 8;
    const int j   = jbase + u;

    // --- load weights into registers (held for entire scan) ---
    float2 w[3][16];
    {
        const int kbase = kg * 32;
#pragma unroll
        for (int g = 0; g < 3; g++)
#pragma unroll
            for (int kk2 = 0; kk2 < 16; kk2++) {
                int k = kbase + 2 * kk2;
                w[g][kk2].x = __ldg(Wh + (size_t)k       * G3_ + g * H_ + j);
                w[g][kk2].y = __ldg(Wh + (size_t)(k + 1) * G3_ + g * H_ + j);
            }
    }
    // biases to smem
    if (tid < 24) sBh[tid] = bh[(tid >> 3) * H_ + jbase + (tid & 7)];
    // zero initial hidden state for owned units
    for (int i = tid; i < B_ * 8; i += SC_THREADS) {
        int b = i >> 3, uu = i & 7;
        g_h[0][b * H_ + jbase + uu] = 0.0f;
    }
    grid_barrier(c);

    const uint32_t sact_base = (uint32_t)__cvta_generic_to_shared(sAct);

    for (int t = 0; t < T_; t++) {
        const float* hprev = g_h[t & 1];
        float*       hnext = g_h[(t + 1) & 1];

        // prefetch xg (1536 floats) and h_old (512 floats) into smem
        if (tid < 192) {
            int b = tid / 3, g = tid - 3 * b;
            const float* src = xg + ((size_t)b * T_ + t) * G3_ + g * H_ + jbase;
            float4 v0 = __ldg((const float4*)src);
            float4 v1 = __ldg((const float4*)(src + 4));
            *(float4*)&sXg[(b * 3 + g) * 8]     = v0;
            *(float4*)&sXg[(b * 3 + g) * 8 + 4] = v1;
        }
        if (tid < 64) {
            const float* src = hprev + (size_t)tid * H_ + jbase;
            float4 v0 = *(const float4*)src;
            float4 v1 = *(const float4*)(src + 4);
            *(float4*)&sHold[tid * 8]     = v0;
            *(float4*)&sHold[tid * 8 + 4] = v1;
        }

        // kick round 0 staging: rows [0,8) of hprev into buf 0
        {
            const float* srcb = hprev;
#pragma unroll
            for (int q = 0; q < 8; q++) {
                int i = tid + 256 * q;
                int row = i >> 8, col4 = i & 255;
                cp_async16(sact_base + (uint32_t)((row * 1024 + col4 * 4) * 4),
                           srcb + (size_t)row * H_ + col4 * 4);
            }
            cp_commit();
        }

        for (int r = 0; r < 8; r++) {
            cp_wait0();
            __syncthreads();                      // A: staged acts visible
            if (r + 1 < 8) {
                const float* srcb = hprev + (size_t)(r + 1) * 8 * H_;
                uint32_t dstb = sact_base + (uint32_t)((((r + 1) & 1) * 8192) * 4);
#pragma unroll
                for (int q = 0; q < 8; q++) {
                    int i = tid + 256 * q;
                    int row = i >> 8, col4 = i & 255;
                    cp_async16(dstb + (uint32_t)((row * 1024 + col4 * 4) * 4),
                               srcb + (size_t)row * H_ + col4 * 4);
                }
                cp_commit();
            }

            // compute: 8 batches x 3 gates over this thread's 32 ks
            float2 acc[8][3];
#pragma unroll
            for (int b = 0; b < 8; b++)
#pragma unroll
                for (int g = 0; g < 3; g++) acc[b][g] = make_float2(0.f, 0.f);

            const float* base = sAct + (r & 1) * 8192 + kg * 32;
#pragma unroll
            for (int kk4 = 0; kk4 < 8; kk4++) {
#pragma unroll
                for (int b = 0; b < 8; b++) {
                    float4 av = *(const float4*)(base + b * 1024 + kk4 * 4);
                    float2 alo = make_float2(av.x, av.y);
                    float2 ahi = make_float2(av.z, av.w);
#pragma unroll
                    for (int g = 0; g < 3; g++) {
                        acc[b][g] = ffma2(alo, w[g][2 * kk4],     acc[b][g]);
                        acc[b][g] = ffma2(ahi, w[g][2 * kk4 + 1], acc[b][g]);
                    }
                }
            }

            // reduce: collapse float2, 1 shuffle level (kg ^ 1 lives at lane ^ 8)
#pragma unroll
            for (int b = 0; b < 8; b++)
#pragma unroll
                for (int g = 0; g < 3; g++) {
                    float v = acc[b][g].x + acc[b][g].y;
                    v += __shfl_xor_sync(0xffffffffu, v, 8);
                    if ((kg & 1) == 0)
                        sPart[((b * 8 + u) * 3 + g) * 17 + (kg >> 1)] = v;
                }
            __syncthreads();                      // B: partials visible

            // stage 2: 64 threads finish reduction + GRU update
            if (tid < 64) {
                int b8 = tid >> 3, u2 = tid & 7;
                const float* pp = &sPart[((b8 * 8 + u2) * 3) * 17];
                float s0 = 0.f, s1 = 0.f, s2 = 0.f;
#pragma unroll
                for (int kk = 0; kk < 16; kk++) {
                    s0 += pp[kk];
                    s1 += pp[17 + kk];
                    s2 += pp[34 + kk];
                }
                int b = 8 * r + b8;
                float xr = sXg[(b * 3 + 0) * 8 + u2];
                float xz = sXg[(b * 3 + 1) * 8 + u2];
                float xn = sXg[(b * 3 + 2) * 8 + u2];
                float rr = fast_sigmoid(xr + s0 + sBh[u2]);
                float zz = fast_sigmoid(xz + s1 + sBh[8 + u2]);
                float nn = fast_tanh(xn + rr * (s2 + sBh[16 + u2]));
                float hold = sHold[b * 8 + u2];
                float hnew = (1.0f - zz) * nn + zz * hold;
                int jj = jbase + u2;
                hnext[(size_t)b * H_ + jj] = hnew;
                hout[((size_t)b * T_ + t) * H_ + jj] = hnew;
                if (t == T_ - 1) state_out[(size_t)b * H_ + jj] = hnew;
            }
        }
        grid_barrier(c);
    }
}

// ---------------- launch ----------------
extern "C" void kernel_launch(void* const* d_in, const int* in_sizes, int n_in,
                              void* d_out, int out_size)
{
    const void*  x   = d_in[0];
    const float* emb = (const float*)d_in[1];
    const float* Wx0 = (const float*)d_in[2];
    const float* Wh0 = (const float*)d_in[3];
    const float* bx0 = (const float*)d_in[4];
    const float* bh0 = (const float*)d_in[5];
    const float* Wx  = (const float*)d_in[6];
    const float* Wh  = (const float*)d_in[7];
    const float* bx  = (const float*)d_in[8];
    const float* bh  = (const float*)d_in[9];

    float* out     = (float*)d_out;
    float* enc_out = out;                                  // [B,T,H]
    float* states  = out + (size_t)M_ * H_;                // [4,B,H]
    float* mask    = states + (size_t)4 * B_ * H_;         // [B,T]

    void *p_act, *p_xg, *p_b0, *p_b1;
    cudaGetSymbolAddress(&p_act, g_act);
    cudaGetSymbolAddress(&p_xg,  g_xg);
    cudaGetSymbolAddress(&p_b0,  g_buf0);
    cudaGetSymbolAddress(&p_b1,  g_buf1);
    float* act = (float*)p_act;
    float* xg  = (float*)p_xg;
    float* b0  = (float*)p_b0;
    float* b1  = (float*)p_b1;

    cudaFuncSetAttribute(scan_kernel, cudaFuncAttributeMaxDynamicSharedMemorySize,
                         SC_SMEM_BYTES);

    detect_kernel<<<1, 64>>>((const int*)x);
    embed_kernel<<<M_, 128>>>(x, emb, mask);

    // layer 0: E -> H
    gemm_bias_kernel<<<dim3(G3_ / 128, M_ / 128), 256>>>(act, Wx0, bx0, xg, E_);
    scan_kernel<<<SC_CTAS, SC_THREADS, SC_SMEM_BYTES>>>(xg, Wh0, bh0, b0, states);

    // layers 1..3: H -> H
    for (int l = 0; l < 3; l++) {
        const float* in_act = (l == 1) ? b1 : b0;
        float* out_act      = (l == 2) ? enc_out : ((l == 0) ? b1 : b0);
        gemm_bias_kernel<<<dim3(G3_ / 128, M_ / 128), 256>>>(
            in_act, Wx + (size_t)l * H_ * G3_, bx + (size_t)l * G3_, xg, H_);
        scan_kernel<<<SC_CTAS, SC_THREADS, SC_SMEM_BYTES>>>(
            xg, Wh + (size_t)l * H_ * G3_, bh + (size_t)l * G3_,
            out_act, states + (size_t)(l + 1) * B_ * H_);
    }
}

// round 7
// speedup vs baseline: 1.7740x; 1.1974x over previous
#include <cuda_runtime.h>
#include <cuda_bf16.h>
#include <cstdint>
#include <cmath>

#define B_  64
#define T_  512
#define E_  512
#define H_  1024
#define M_  (B_*T_)     // 32768 rows
#define G3_ (3*H_)      // 3072

// single extern shared symbol for ALL kernels
extern __shared__ char hx_smem[];

// ---------------- scratch ----------------
__device__ float g_act[(size_t)M_ * E_];
__device__ float g_xg [(size_t)M_ * G3_];
__device__ float g_buf0[(size_t)M_ * H_];
__device__ float g_buf1[(size_t)M_ * H_];
__device__ float g_h[2][B_ * H_];
__device__ __nv_bfloat16 g_ahi[(size_t)M_ * H_];
__device__ __nv_bfloat16 g_alo[(size_t)M_ * H_];
__device__ __nv_bfloat16 g_wthi[(size_t)G3_ * H_]; // W^T [N][K]
__device__ __nv_bfloat16 g_wtlo[(size_t)G3_ * H_];
__device__ unsigned g_grp_cnt[8];
__device__ unsigned g_root_cnt = 0;
__device__ unsigned g_bar_gen  = 0;
__device__ int g_x_is_i64 = 1;

// ---------------- helpers ----------------
union F2U64 { float2 f2; unsigned long long u; };
__device__ __forceinline__ float2 ffma2(float2 a, float2 b, float2 c) {
    F2U64 A, Bv, C, D;
    A.f2 = a; Bv.f2 = b; C.f2 = c;
    asm("fma.rn.f32x2 %0, %1, %2, %3;" : "=l"(D.u) : "l"(A.u), "l"(Bv.u), "l"(C.u));
    return D.f2;
}
__device__ __forceinline__ float fast_tanh(float x) {
    float y; asm("tanh.approx.f32 %0, %1;" : "=f"(y) : "f"(x)); return y;
}
__device__ __forceinline__ float fast_sigmoid(float x) {
    return 0.5f * fast_tanh(0.5f * x) + 0.5f;
}
__device__ __forceinline__ uint32_t smem_u32(const void* p) {
    return (uint32_t)__cvta_generic_to_shared(p);
}
__device__ __forceinline__ void cp_async16(uint32_t smem_addr, const void* gptr) {
    asm volatile("cp.async.cg.shared.global [%0], [%1], 16;"
                 :: "r"(smem_addr), "l"(gptr));
}
__device__ __forceinline__ void cp_commit() { asm volatile("cp.async.commit_group;"); }
__device__ __forceinline__ void cp_wait0() { asm volatile("cp.async.wait_group 0;"); }
__device__ __forceinline__ void cp_wait1() { asm volatile("cp.async.wait_group 1;"); }

#define LDSM_X4(r, addr) \
    asm volatile("ldmatrix.sync.aligned.m8n8.x4.shared.b16 {%0,%1,%2,%3}, [%4];" \
        : "=r"((r)[0]), "=r"((r)[1]), "=r"((r)[2]), "=r"((r)[3]) : "r"(addr))

#define MMA16816(d, a, b0, b1) \
    asm volatile("mma.sync.aligned.m16n8k16.row.col.f32.bf16.bf16.f32 " \
        "{%0,%1,%2,%3}, {%4,%5,%6,%7}, {%8,%9}, {%0,%1,%2,%3};" \
        : "+f"((d)[0]), "+f"((d)[1]), "+f"((d)[2]), "+f"((d)[3]) \
        : "r"((a)[0]), "r"((a)[1]), "r"((a)[2]), "r"((a)[3]), "r"(b0), "r"(b1))

// ---------------- int64-vs-int32 detection ----------------
__global__ void detect_kernel(const int* __restrict__ x32) {
    __shared__ int nz;
    if (threadIdx.x == 0) nz = 0;
    __syncthreads();
    if (x32[2 * threadIdx.x + 1] != 0) atomicExch(&nz, 1);
    __syncthreads();
    if (threadIdx.x == 0) g_x_is_i64 = (nz == 0) ? 1 : 0;
}

// ---------------- embedding gather + pad mask ----------------
__global__ __launch_bounds__(128) void embed_kernel(
    const void* __restrict__ xraw, const float* __restrict__ emb,
    float* __restrict__ mask_out)
{
    const int r = blockIdx.x;
    long long idx;
    if (g_x_is_i64) idx = ((const long long*)xraw)[r];
    else            idx = (long long)((const int*)xraw)[r];
    const float4* src = (const float4*)(emb + (size_t)idx * E_);
    float4* dst = (float4*)(g_act + (size_t)r * E_);
    dst[threadIdx.x] = src[threadIdx.x];
    if (threadIdx.x == 0) mask_out[r] = (idx != 0) ? 1.0f : 0.0f;
}

// ---------------- fp32 -> bf16 hi/lo split ----------------
__global__ __launch_bounds__(256) void convertA_kernel(
    const float* __restrict__ A, __nv_bfloat16* __restrict__ hi,
    __nv_bfloat16* __restrict__ lo)
{
    size_t i = (size_t)blockIdx.x * 256 + threadIdx.x;
    float4 v = ((const float4*)A)[i];
    union { __nv_bfloat16 b[4]; uint2 u; } H, L;
    float f[4] = {v.x, v.y, v.z, v.w};
#pragma unroll
    for (int q = 0; q < 4; q++) {
        __nv_bfloat16 h = __float2bfloat16_rn(f[q]);
        H.b[q] = h;
        L.b[q] = __float2bfloat16_rn(f[q] - __bfloat162float(h));
    }
    ((uint2*)hi)[i] = H.u;
    ((uint2*)lo)[i] = L.u;
}

// ---------------- W [K][3072] fp32 -> W^T [3072][K] bf16 hi/lo ----------------
__global__ __launch_bounds__(256) void convertWT_kernel(
    const float* __restrict__ W, __nv_bfloat16* __restrict__ Thi,
    __nv_bfloat16* __restrict__ Tlo, int K)
{
    __shared__ float t[32][33];
    const int n0 = blockIdx.x * 32, k0 = blockIdx.y * 32;
    const int tx = threadIdx.x & 31, ty = threadIdx.x >> 5;
#pragma unroll
    for (int i = 0; i < 32; i += 8)
        t[ty + i][tx] = W[(size_t)(k0 + ty + i) * G3_ + n0 + tx];
    __syncthreads();
#pragma unroll
    for (int i = 0; i < 32; i += 8) {
        float v = t[tx][ty + i];
        __nv_bfloat16 h = __float2bfloat16_rn(v);
        size_t o = (size_t)(n0 + ty + i) * K + k0 + tx;
        Thi[o] = h;
        Tlo[o] = __float2bfloat16_rn(v - __bfloat162float(h));
    }
}

// ---------------- bf16-split mma.sync GEMM: C[M,3072] = A @ W^T + bias -------
// 128x128 tile, 256 thr (8 warps = 2m x 4n), K chunks of 32, double-buffered.
// smem per tile: 128 rows x 32 bf16, row stride 40 bf16 (80B) -> 10240 B.
#define GT_TILE   10240
#define GT_STAGE  (4 * GT_TILE)        // Ahi, Alo, Bhi, Blo
#define GT_SMEM   (2 * GT_STAGE)       // 81920 B

__global__ __launch_bounds__(256, 1) void gemm_mma_kernel(
    const __nv_bfloat16* __restrict__ Ahi, const __nv_bfloat16* __restrict__ Alo,
    const __nv_bfloat16* __restrict__ Bhi, const __nv_bfloat16* __restrict__ Blo,
    const float* __restrict__ bias, float* __restrict__ C, int K)
{
    const uint32_t sb = smem_u32(hx_smem);
    const int tid = threadIdx.x;
    const int wid = tid >> 5, lid = tid & 31;
    const int wm = wid & 1, wn = wid >> 1;          // 2 x 4 warp grid
    const int n0 = blockIdx.x * 128, m0 = blockIdx.y * 128;
    const int nch = K >> 5;

    float acc[4][4][4];
#pragma unroll
    for (int mf = 0; mf < 4; mf++)
#pragma unroll
        for (int n8 = 0; n8 < 4; n8++)
#pragma unroll
            for (int q = 0; q < 4; q++) acc[mf][n8][q] = 0.0f;

    // FIXED staging: 128 rows x 4 x 16B segments per tile = 512 cp16 / tile,
    // 2 per thread per tile.
    auto stage = [&](int kc) {
        const uint32_t st = sb + (uint32_t)(kc & 1) * GT_STAGE;
        const int koff = kc * 32;
#pragma unroll
        for (int q = 0; q < 2; q++) {
            int i = tid + 256 * q;
            int row = i >> 2, seg = i & 3;
            uint32_t d = st + (uint32_t)(row * 80 + seg * 16);
            size_t ao = (size_t)(m0 + row) * K + koff + seg * 8;
            size_t bo = (size_t)(n0 + row) * K + koff + seg * 8;
            cp_async16(d,               Ahi + ao);
            cp_async16(d + GT_TILE,     Alo + ao);
            cp_async16(d + 2 * GT_TILE, Bhi + bo);
            cp_async16(d + 3 * GT_TILE, Blo + bo);
        }
        cp_commit();
    };

    // per-lane ldmatrix address components
    const int a_row = wm * 64 + (lid & 15);         // + mf*16
    const int a_colb = (lid >> 4) * 16;             // byte offset within k16
    const int b_row = wn * 32 + ((lid >> 4) << 3) + (lid & 7);   // + nf*16
    const int b_colb = ((lid >> 3) & 1) * 16;

    stage(0);
    for (int c = 0; c < nch; c++) {
        if (c + 1 < nch) { stage(c + 1); cp_wait1(); }
        else             { cp_wait0(); }
        __syncthreads();

        const uint32_t st = sb + (uint32_t)(c & 1) * GT_STAGE;
#pragma unroll
        for (int ks = 0; ks < 2; ks++) {
            const int kb = ks * 32;                  // 16 bf16 = 32 bytes
            uint32_t ah[4][4], al[4][4], bh[2][4], bl[2][4];
#pragma unroll
            for (int mf = 0; mf < 4; mf++) {
                uint32_t addr = st + (uint32_t)((a_row + mf * 16) * 80 + kb + a_colb);
                LDSM_X4(ah[mf], addr);
                LDSM_X4(al[mf], addr + GT_TILE);
            }
#pragma unroll
            for (int nf = 0; nf < 2; nf++) {
                uint32_t addr = st + 2 * GT_TILE +
                                (uint32_t)((b_row + nf * 16) * 80 + kb + b_colb);
                LDSM_X4(bh[nf], addr);
                LDSM_X4(bl[nf], addr + GT_TILE);
            }
#pragma unroll
            for (int mf = 0; mf < 4; mf++)
#pragma unroll
                for (int n8 = 0; n8 < 4; n8++) {
                    const int nf = n8 >> 1, hh = (n8 & 1) * 2;
                    MMA16816(acc[mf][n8], ah[mf], bh[nf][hh], bh[nf][hh + 1]);
                    MMA16816(acc[mf][n8], ah[mf], bl[nf][hh], bl[nf][hh + 1]);
                    MMA16816(acc[mf][n8], al[mf], bh[nf][hh], bh[nf][hh + 1]);
                }
        }
        __syncthreads();
    }

    // epilogue: fragment (mf,n8): rows (lid>>2)+{0,8}, cols (lid&3)*2+{0,1}
#pragma unroll
    for (int mf = 0; mf < 4; mf++) {
        const int gm = m0 + wm * 64 + mf * 16 + (lid >> 2);
#pragma unroll
        for (int n8 = 0; n8 < 4; n8++) {
            const int gc = n0 + wn * 32 + n8 * 8 + (lid & 3) * 2;
            float2 bb = *(const float2*)(bias + gc);
            float2 v0, v1;
            v0.x = acc[mf][n8][0] + bb.x; v0.y = acc[mf][n8][1] + bb.y;
            v1.x = acc[mf][n8][2] + bb.x; v1.y = acc[mf][n8][3] + bb.y;
            *(float2*)(C + (size_t)gm * G3_ + gc)       = v0;
            *(float2*)(C + (size_t)(gm + 8) * G3_ + gc) = v1;
        }
    }
}

// ---------------- persistent GRU scan (register-resident weights) ----------------
#define SC_CTAS    128
#define SC_THREADS 256
#define SA_ACT   0
#define SA_PART  (SA_ACT + 2*8*1024)
#define SA_XG    (SA_PART + 64*3*17)
#define SA_HOLD  (SA_XG + 64*3*8)
#define SA_BH    (SA_HOLD + 64*8)
#define SC_SMEM_FLOATS (SA_BH + 24)
#define SC_SMEM_BYTES  (SC_SMEM_FLOATS * 4)

__device__ __forceinline__ void grid_barrier(int c) {
    __syncthreads();
    if (threadIdx.x == 0) {
        __threadfence();
        unsigned gen = *(volatile unsigned*)&g_bar_gen;
        int grp = c & 7;
        if (atomicAdd(&g_grp_cnt[grp], 1u) == 15u) {
            if (atomicAdd(&g_root_cnt, 1u) == 7u) {
                atomicExch(&g_root_cnt, 0u);
#pragma unroll
                for (int i = 0; i < 8; i++) atomicExch(&g_grp_cnt[i], 0u);
                __threadfence();
                atomicAdd(&g_bar_gen, 1u);
            }
        }
        while (*(volatile unsigned*)&g_bar_gen == gen) __nanosleep(32);
        __threadfence();
    }
    __syncthreads();
}

__global__ __launch_bounds__(SC_THREADS, 1) void scan_kernel(
    const float* __restrict__ xg, const float* __restrict__ Wh,
    const float* __restrict__ bh, float* __restrict__ hout,
    float* __restrict__ state_out)
{
    float* smem  = (float*)hx_smem;
    float* sAct  = smem + SA_ACT;
    float* sPart = smem + SA_PART;
    float* sXg   = smem + SA_XG;
    float* sHold = smem + SA_HOLD;
    float* sBh   = smem + SA_BH;

    const int c   = blockIdx.x;
    const int tid = threadIdx.x;
    const int u   = tid & 7;
    const int kg  = tid >> 3;
    const int jbase = c * 8;
    const int j   = jbase + u;

    float2 w[3][16];
    {
        const int kbase = kg * 32;
#pragma unroll
        for (int g = 0; g < 3; g++)
#pragma unroll
            for (int kk2 = 0; kk2 < 16; kk2++) {
                int k = kbase + 2 * kk2;
                w[g][kk2].x = __ldg(Wh + (size_t)k       * G3_ + g * H_ + j);
                w[g][kk2].y = __ldg(Wh + (size_t)(k + 1) * G3_ + g * H_ + j);
            }
    }
    if (tid < 24) sBh[tid] = bh[(tid >> 3) * H_ + jbase + (tid & 7)];
    for (int i = tid; i < B_ * 8; i += SC_THREADS) {
        int b = i >> 3, uu = i & 7;
        g_h[0][b * H_ + jbase + uu] = 0.0f;
    }
    grid_barrier(c);

    const uint32_t sact_base = smem_u32(sAct);

    for (int t = 0; t < T_; t++) {
        const float* hprev = g_h[t & 1];
        float*       hnext = g_h[(t + 1) & 1];

        if (tid < 192) {
            int b = tid / 3, g = tid - 3 * b;
            const float* src = xg + ((size_t)b * T_ + t) * G3_ + g * H_ + jbase;
            float4 v0 = __ldg((const float4*)src);
            float4 v1 = __ldg((const float4*)(src + 4));
            *(float4*)&sXg[(b * 3 + g) * 8]     = v0;
            *(float4*)&sXg[(b * 3 + g) * 8 + 4] = v1;
        }
        if (tid < 64) {
            const float* src = hprev + (size_t)tid * H_ + jbase;
            float4 v0 = *(const float4*)src;
            float4 v1 = *(const float4*)(src + 4);
            *(float4*)&sHold[tid * 8]     = v0;
            *(float4*)&sHold[tid * 8 + 4] = v1;
        }
        {
            const float* srcb = hprev;
#pragma unroll
            for (int q = 0; q < 8; q++) {
                int i = tid + 256 * q;
                int row = i >> 8, col4 = i & 255;
                cp_async16(sact_base + (uint32_t)((row * 1024 + col4 * 4) * 4),
                           srcb + (size_t)row * H_ + col4 * 4);
            }
            cp_commit();
        }

        for (int r = 0; r < 8; r++) {
            cp_wait0();
            __syncthreads();
            if (r + 1 < 8) {
                const float* srcb = hprev + (size_t)(r + 1) * 8 * H_;
                uint32_t dstb = sact_base + (uint32_t)((((r + 1) & 1) * 8192) * 4);
#pragma unroll
                for (int q = 0; q < 8; q++) {
                    int i = tid + 256 * q;
                    int row = i >> 8, col4 = i & 255;
                    cp_async16(dstb + (uint32_t)((row * 1024 + col4 * 4) * 4),
                               srcb + (size_t)row * H_ + col4 * 4);
                }
                cp_commit();
            }

            float2 acc[8][3];
#pragma unroll
            for (int b = 0; b < 8; b++)
#pragma unroll
                for (int g = 0; g < 3; g++) acc[b][g] = make_float2(0.f, 0.f);

            const float* base = sAct + (r & 1) * 8192 + kg * 32;
#pragma unroll
            for (int kk4 = 0; kk4 < 8; kk4++) {
#pragma unroll
                for (int b = 0; b < 8; b++) {
                    float4 av = *(const float4*)(base + b * 1024 + kk4 * 4);
                    float2 alo = make_float2(av.x, av.y);
                    float2 ahi = make_float2(av.z, av.w);
#pragma unroll
                    for (int g = 0; g < 3; g++) {
                        acc[b][g] = ffma2(alo, w[g][2 * kk4],     acc[b][g]);
                        acc[b][g] = ffma2(ahi, w[g][2 * kk4 + 1], acc[b][g]);
                    }
                }
            }

#pragma unroll
            for (int b = 0; b < 8; b++)
#pragma unroll
                for (int g = 0; g < 3; g++) {
                    float v = acc[b][g].x + acc[b][g].y;
                    v += __shfl_xor_sync(0xffffffffu, v, 8);
                    if ((kg & 1) == 0)
                        sPart[((b * 8 + u) * 3 + g) * 17 + (kg >> 1)] = v;
                }
            __syncthreads();

            if (tid < 64) {
                int b8 = tid >> 3, u2 = tid & 7;
                const float* pp = &sPart[((b8 * 8 + u2) * 3) * 17];
                float s0 = 0.f, s1 = 0.f, s2 = 0.f;
#pragma unroll
                for (int kk = 0; kk < 16; kk++) {
                    s0 += pp[kk];
                    s1 += pp[17 + kk];
                    s2 += pp[34 + kk];
                }
                int b = 8 * r + b8;
                float xr = sXg[(b * 3 + 0) * 8 + u2];
                float xz = sXg[(b * 3 + 1) * 8 + u2];
                float xn = sXg[(b * 3 + 2) * 8 + u2];
                float rr = fast_sigmoid(xr + s0 + sBh[u2]);
                float zz = fast_sigmoid(xz + s1 + sBh[8 + u2]);
                float nn = fast_tanh(xn + rr * (s2 + sBh[16 + u2]));
                float hold = sHold[b * 8 + u2];
                float hnew = (1.0f - zz) * nn + zz * hold;
                int jj = jbase + u2;
                hnext[(size_t)b * H_ + jj] = hnew;
                hout[((size_t)b * T_ + t) * H_ + jj] = hnew;
                if (t == T_ - 1) state_out[(size_t)b * H_ + jj] = hnew;
            }
        }
        grid_barrier(c);
    }
}

// ---------------- launch ----------------
extern "C" void kernel_launch(void* const* d_in, const int* in_sizes, int n_in,
                              void* d_out, int out_size)
{
    const void*  x   = d_in[0];
    const float* emb = (const float*)d_in[1];
    const float* Wx0 = (const float*)d_in[2];
    const float* Wh0 = (const float*)d_in[3];
    const float* bx0 = (const float*)d_in[4];
    const float* bh0 = (const float*)d_in[5];
    const float* Wx  = (const float*)d_in[6];
    const float* Wh  = (const float*)d_in[7];
    const float* bx  = (const float*)d_in[8];
    const float* bh  = (const float*)d_in[9];

    float* out     = (float*)d_out;
    float* enc_out = out;
    float* states  = out + (size_t)M_ * H_;
    float* mask    = states + (size_t)4 * B_ * H_;

    void *p_act, *p_xg, *p_b0, *p_b1, *p_ahi, *p_alo, *p_whi, *p_wlo;
    cudaGetSymbolAddress(&p_act, g_act);
    cudaGetSymbolAddress(&p_xg,  g_xg);
    cudaGetSymbolAddress(&p_b0,  g_buf0);
    cudaGetSymbolAddress(&p_b1,  g_buf1);
    cudaGetSymbolAddress(&p_ahi, g_ahi);
    cudaGetSymbolAddress(&p_alo, g_alo);
    cudaGetSymbolAddress(&p_whi, g_wthi);
    cudaGetSymbolAddress(&p_wlo, g_wtlo);
    float* act = (float*)p_act;
    float* xg  = (float*)p_xg;
    float* b0  = (float*)p_b0;
    float* b1  = (float*)p_b1;
    __nv_bfloat16* ahi = (__nv_bfloat16*)p_ahi;
    __nv_bfloat16* alo = (__nv_bfloat16*)p_alo;
    __nv_bfloat16* whi = (__nv_bfloat16*)p_whi;
    __nv_bfloat16* wlo = (__nv_bfloat16*)p_wlo;

    cudaFuncSetAttribute(scan_kernel, cudaFuncAttributeMaxDynamicSharedMemorySize,
                         SC_SMEM_BYTES);
    cudaFuncSetAttribute(gemm_mma_kernel, cudaFuncAttributeMaxDynamicSharedMemorySize,
                         GT_SMEM);

    detect_kernel<<<1, 64>>>((const int*)x);
    embed_kernel<<<M_, 128>>>(x, emb, mask);

    // layer 0: E=512 -> H
    convertA_kernel<<<(M_ * E_) / 1024, 256>>>(act, ahi, alo);
    convertWT_kernel<<<dim3(G3_ / 32, E_ / 32), 256>>>(Wx0, whi, wlo, E_);
    gemm_mma_kernel<<<dim3(G3_ / 128, M_ / 128), 256, GT_SMEM>>>(
        ahi, alo, whi, wlo, bx0, xg, E_);
    scan_kernel<<<SC_CTAS, SC_THREADS, SC_SMEM_BYTES>>>(xg, Wh0, bh0, b0, states);

    // layers 1..3: H -> H
    for (int l = 0; l < 3; l++) {
        const float* in_act = (l == 1) ? b1 : b0;
        float* out_act      = (l == 2) ? enc_out : ((l == 0) ? b1 : b0);
        convertA_kernel<<<(M_ * H_) / 1024, 256>>>(in_act, ahi, alo);
        convertWT_kernel<<<dim3(G3_ / 32, H_ / 32), 256>>>(
            Wx + (size_t)l * H_ * G3_, whi, wlo, H_);
        gemm_mma_kernel<<<dim3(G3_ / 128, M_ / 128), 256, GT_SMEM>>>(
            ahi, alo, whi, wlo, bx + (size_t)l * G3_, xg, H_);
        scan_kernel<<<SC_CTAS, SC_THREADS, SC_SMEM_BYTES>>>(
            xg, Wh + (size_t)l * H_ * G3_, bh + (size_t)l * G3_,
            out_act, states + (size_t)(l + 1) * B_ * H_);
    }
}

// round 8
// speedup vs baseline: 1.7954x; 1.0120x over previous
#include <cuda_runtime.h>
#include <cuda_bf16.h>
#include <cstdint>
#include <cmath>

#define B_  64
#define T_  512
#define E_  512
#define H_  1024
#define M_  (B_*T_)     // 32768 rows
#define G3_ (3*H_)      // 3072

extern __shared__ char hx_smem[];

// ---------------- scratch ----------------
__device__ float g_xg [(size_t)M_ * G3_];
__device__ float g_buf0[(size_t)M_ * H_];
__device__ float g_h[2][B_ * H_];
__device__ __nv_bfloat16 g_ahi[(size_t)M_ * H_];
__device__ __nv_bfloat16 g_alo[(size_t)M_ * H_];
__device__ __nv_bfloat16 g_wthi[(size_t)G3_ * H_]; // W^T [N][K]
__device__ __nv_bfloat16 g_wtlo[(size_t)G3_ * H_];
__device__ unsigned g_grp_cnt[8];
__device__ unsigned g_root_cnt = 0;
__device__ unsigned g_bar_gen  = 0;
__device__ int g_x_is_i64 = 1;

// ---------------- helpers ----------------
union F2U64 { float2 f2; unsigned long long u; };
__device__ __forceinline__ float2 ffma2(float2 a, float2 b, float2 c) {
    F2U64 A, Bv, C, D;
    A.f2 = a; Bv.f2 = b; C.f2 = c;
    asm("fma.rn.f32x2 %0, %1, %2, %3;" : "=l"(D.u) : "l"(A.u), "l"(Bv.u), "l"(C.u));
    return D.f2;
}
__device__ __forceinline__ float fast_tanh(float x) {
    float y; asm("tanh.approx.f32 %0, %1;" : "=f"(y) : "f"(x)); return y;
}
__device__ __forceinline__ float fast_sigmoid(float x) {
    return 0.5f * fast_tanh(0.5f * x) + 0.5f;
}
__device__ __forceinline__ uint32_t smem_u32(const void* p) {
    return (uint32_t)__cvta_generic_to_shared(p);
}
__device__ __forceinline__ void cp_async16(uint32_t smem_addr, const void* gptr) {
    asm volatile("cp.async.cg.shared.global [%0], [%1], 16;"
                 :: "r"(smem_addr), "l"(gptr));
}
__device__ __forceinline__ void cp_commit() { asm volatile("cp.async.commit_group;"); }
__device__ __forceinline__ void cp_wait0() { asm volatile("cp.async.wait_group 0;"); }
__device__ __forceinline__ void cp_wait1() { asm volatile("cp.async.wait_group 1;"); }

#define LDSM_X4(r, addr) \
    asm volatile("ldmatrix.sync.aligned.m8n8.x4.shared.b16 {%0,%1,%2,%3}, [%4];" \
        : "=r"((r)[0]), "=r"((r)[1]), "=r"((r)[2]), "=r"((r)[3]) : "r"(addr))

#define MMA16816(d, a, b0, b1) \
    asm volatile("mma.sync.aligned.m16n8k16.row.col.f32.bf16.bf16.f32 " \
        "{%0,%1,%2,%3}, {%4,%5,%6,%7}, {%8,%9}, {%0,%1,%2,%3};" \
        : "+f"((d)[0]), "+f"((d)[1]), "+f"((d)[2]), "+f"((d)[3]) \
        : "r"((a)[0]), "r"((a)[1]), "r"((a)[2]), "r"((a)[3]), "r"(b0), "r"(b1))

// ---------------- int64-vs-int32 detection ----------------
__global__ void detect_kernel(const int* __restrict__ x32) {
    __shared__ int nz;
    if (threadIdx.x == 0) nz = 0;
    __syncthreads();
    if (x32[2 * threadIdx.x + 1] != 0) atomicExch(&nz, 1);
    __syncthreads();
    if (threadIdx.x == 0) g_x_is_i64 = (nz == 0) ? 1 : 0;
}

// ---------------- embedding gather (direct bf16 hi/lo) + pad mask ----------------
__global__ __launch_bounds__(128) void embed_kernel(
    const void* __restrict__ xraw, const float* __restrict__ emb,
    __nv_bfloat16* __restrict__ ahi, __nv_bfloat16* __restrict__ alo,
    float* __restrict__ mask_out)
{
    const int r = blockIdx.x;
    long long idx;
    if (g_x_is_i64) idx = ((const long long*)xraw)[r];
    else            idx = (long long)((const int*)xraw)[r];
    float4 v = ((const float4*)(emb + (size_t)idx * E_))[threadIdx.x];
    union { __nv_bfloat16 b[4]; uint2 u; } Hh, Ll;
    float f[4] = {v.x, v.y, v.z, v.w};
#pragma unroll
    for (int q = 0; q < 4; q++) {
        __nv_bfloat16 h = __float2bfloat16_rn(f[q]);
        Hh.b[q] = h;
        Ll.b[q] = __float2bfloat16_rn(f[q] - __bfloat162float(h));
    }
    ((uint2*)(ahi + (size_t)r * E_))[threadIdx.x] = Hh.u;
    ((uint2*)(alo + (size_t)r * E_))[threadIdx.x] = Ll.u;
    if (threadIdx.x == 0) mask_out[r] = (idx != 0) ? 1.0f : 0.0f;
}

// ---------------- W [K][3072] fp32 -> W^T [3072][K] bf16 hi/lo ----------------
__global__ __launch_bounds__(256) void convertWT_kernel(
    const float* __restrict__ W, __nv_bfloat16* __restrict__ Thi,
    __nv_bfloat16* __restrict__ Tlo, int K)
{
    __shared__ float t[32][33];
    const int n0 = blockIdx.x * 32, k0 = blockIdx.y * 32;
    const int tx = threadIdx.x & 31, ty = threadIdx.x >> 5;
#pragma unroll
    for (int i = 0; i < 32; i += 8)
        t[ty + i][tx] = W[(size_t)(k0 + ty + i) * G3_ + n0 + tx];
    __syncthreads();
#pragma unroll
    for (int i = 0; i < 32; i += 8) {
        float v = t[tx][ty + i];
        __nv_bfloat16 h = __float2bfloat16_rn(v);
        size_t o = (size_t)(n0 + ty + i) * K + k0 + tx;
        Thi[o] = h;
        Tlo[o] = __float2bfloat16_rn(v - __bfloat162float(h));
    }
}

// ---------------- bf16-split mma.sync GEMM: C[M,3072] = A @ W^T + bias -------
// 128x128 tile, 256 thr (8 warps = 2m x 4n), K chunks of 64, double-buffered.
// tile rows stride 144B (64 bf16 = 128B data + 16B pad) -> conflict-free ldmatrix.
#define GT_TILE   18432                // 128 * 144
#define GT_STAGE  (4 * GT_TILE)        // Ahi, Alo, Bhi, Blo
#define GT_SMEM   (2 * GT_STAGE)       // 147456 B

__global__ __launch_bounds__(256, 1) void gemm_mma_kernel(
    const __nv_bfloat16* __restrict__ Ahi, const __nv_bfloat16* __restrict__ Alo,
    const __nv_bfloat16* __restrict__ Bhi, const __nv_bfloat16* __restrict__ Blo,
    const float* __restrict__ bias, float* __restrict__ C, int K)
{
    const uint32_t sb = smem_u32(hx_smem);
    const int tid = threadIdx.x;
    const int wid = tid >> 5, lid = tid & 31;
    const int wm = wid & 1, wn = wid >> 1;          // 2 x 4 warp grid
    const int n0 = blockIdx.x * 128, m0 = blockIdx.y * 128;
    const int nch = K >> 6;                          // 64-elem chunks

    float acc[4][4][4];
#pragma unroll
    for (int mf = 0; mf < 4; mf++)
#pragma unroll
        for (int n8 = 0; n8 < 4; n8++)
#pragma unroll
            for (int q = 0; q < 4; q++) acc[mf][n8][q] = 0.0f;

    // staging: 128 rows x 8 x 16B segs per tile = 1024 cp16/tile; 4 iters x 4 tiles/thread
    auto stage = [&](int kc) {
        const uint32_t st = sb + (uint32_t)(kc & 1) * GT_STAGE;
        const int koff = kc * 64;
#pragma unroll
        for (int q = 0; q < 4; q++) {
            int i = tid + 256 * q;
            int row = i >> 3, seg = i & 7;
            uint32_t d = st + (uint32_t)(row * 144 + seg * 16);
            size_t ao = (size_t)(m0 + row) * K + koff + seg * 8;
            size_t bo = (size_t)(n0 + row) * K + koff + seg * 8;
            cp_async16(d,               Ahi + ao);
            cp_async16(d + GT_TILE,     Alo + ao);
            cp_async16(d + 2 * GT_TILE, Bhi + bo);
            cp_async16(d + 3 * GT_TILE, Blo + bo);
        }
        cp_commit();
    };

    // per-lane ldmatrix address components
    const int a_row = wm * 64 + (lid & 15);                      // + mf*16
    const int a_colb = (lid >> 4) * 16;
    const int b_row = wn * 32 + ((lid >> 4) << 3) + (lid & 7);   // + nf*16
    const int b_colb = ((lid >> 3) & 1) * 16;

    stage(0);
    for (int c = 0; c < nch; c++) {
        if (c + 1 < nch) { stage(c + 1); cp_wait1(); }
        else             { cp_wait0(); }
        __syncthreads();

        const uint32_t st = sb + (uint32_t)(c & 1) * GT_STAGE;
#pragma unroll
        for (int ks = 0; ks < 4; ks++) {
            const int kb = ks * 32;                  // 16 bf16 = 32 bytes
            uint32_t ah[4][4], al[4][4], bh[2][4], bl[2][4];
#pragma unroll
            for (int mf = 0; mf < 4; mf++) {
                uint32_t addr = st + (uint32_t)((a_row + mf * 16) * 144 + kb + a_colb);
                LDSM_X4(ah[mf], addr);
                LDSM_X4(al[mf], addr + GT_TILE);
            }
#pragma unroll
            for (int nf = 0; nf < 2; nf++) {
                uint32_t addr = st + 2 * GT_TILE +
                                (uint32_t)((b_row + nf * 16) * 144 + kb + b_colb);
                LDSM_X4(bh[nf], addr);
                LDSM_X4(bl[nf], addr + GT_TILE);
            }
#pragma unroll
            for (int mf = 0; mf < 4; mf++)
#pragma unroll
                for (int n8 = 0; n8 < 4; n8++) {
                    const int nf = n8 >> 1, hh = (n8 & 1) * 2;
                    MMA16816(acc[mf][n8], ah[mf], bh[nf][hh], bh[nf][hh + 1]);
                    MMA16816(acc[mf][n8], ah[mf], bl[nf][hh], bl[nf][hh + 1]);
                    MMA16816(acc[mf][n8], al[mf], bh[nf][hh], bh[nf][hh + 1]);
                }
        }
        __syncthreads();
    }

    // epilogue
#pragma unroll
    for (int mf = 0; mf < 4; mf++) {
        const int gm = m0 + wm * 64 + mf * 16 + (lid >> 2);
#pragma unroll
        for (int n8 = 0; n8 < 4; n8++) {
            const int gc = n0 + wn * 32 + n8 * 8 + (lid & 3) * 2;
            float2 bb = *(const float2*)(bias + gc);
            float2 v0, v1;
            v0.x = acc[mf][n8][0] + bb.x; v0.y = acc[mf][n8][1] + bb.y;
            v1.x = acc[mf][n8][2] + bb.x; v1.y = acc[mf][n8][3] + bb.y;
            *(float2*)(C + (size_t)gm * G3_ + gc)       = v0;
            *(float2*)(C + (size_t)(gm + 8) * G3_ + gc) = v1;
        }
    }
}

// ---------------- persistent GRU scan (reg weights; fused bf16 split out) ----------------
#define SC_CTAS    128
#define SC_THREADS 256
#define SA_ACT   0
#define SA_PART  (SA_ACT + 2*8*1024)
#define SA_XG    (SA_PART + 64*3*17)
#define SA_HOLD  (SA_XG + 64*3*8)
#define SA_BH    (SA_HOLD + 64*8)
#define SC_SMEM_FLOATS (SA_BH + 24)
#define SC_SMEM_BYTES  (SC_SMEM_FLOATS * 4)

__device__ __forceinline__ void grid_barrier(int c) {
    __syncthreads();
    if (threadIdx.x == 0) {
        __threadfence();
        unsigned gen = *(volatile unsigned*)&g_bar_gen;
        int grp = c & 7;
        if (atomicAdd(&g_grp_cnt[grp], 1u) == 15u) {
            if (atomicAdd(&g_root_cnt, 1u) == 7u) {
                atomicExch(&g_root_cnt, 0u);
#pragma unroll
                for (int i = 0; i < 8; i++) atomicExch(&g_grp_cnt[i], 0u);
                __threadfence();
                atomicAdd(&g_bar_gen, 1u);
            }
        }
        while (*(volatile unsigned*)&g_bar_gen == gen) __nanosleep(32);
        __threadfence();
    }
    __syncthreads();
}

__global__ __launch_bounds__(SC_THREADS, 1) void scan_kernel(
    const float* __restrict__ xg, const float* __restrict__ Wh,
    const float* __restrict__ bh, float* __restrict__ hout,
    __nv_bfloat16* __restrict__ ahi, __nv_bfloat16* __restrict__ alo,
    float* __restrict__ state_out)
{
    float* smem  = (float*)hx_smem;
    float* sAct  = smem + SA_ACT;
    float* sPart = smem + SA_PART;
    float* sXg   = smem + SA_XG;
    float* sHold = smem + SA_HOLD;
    float* sBh   = smem + SA_BH;

    const int c   = blockIdx.x;
    const int tid = threadIdx.x;
    const int u   = tid & 7;
    const int kg  = tid >> 3;
    const int jbase = c * 8;
    const int j   = jbase + u;

    float2 w[3][16];
    {
        const int kbase = kg * 32;
#pragma unroll
        for (int g = 0; g < 3; g++)
#pragma unroll
            for (int kk2 = 0; kk2 < 16; kk2++) {
                int k = kbase + 2 * kk2;
                w[g][kk2].x = __ldg(Wh + (size_t)k       * G3_ + g * H_ + j);
                w[g][kk2].y = __ldg(Wh + (size_t)(k + 1) * G3_ + g * H_ + j);
            }
    }
    if (tid < 24) sBh[tid] = bh[(tid >> 3) * H_ + jbase + (tid & 7)];
    for (int i = tid; i < B_ * 8; i += SC_THREADS) {
        int b = i >> 3, uu = i & 7;
        g_h[0][b * H_ + jbase + uu] = 0.0f;
    }
    grid_barrier(c);

    const uint32_t sact_base = smem_u32(sAct);

    for (int t = 0; t < T_; t++) {
        const float* hprev = g_h[t & 1];
        float*       hnext = g_h[(t + 1) & 1];

        if (tid < 192) {
            int b = tid / 3, g = tid - 3 * b;
            const float* src = xg + ((size_t)b * T_ + t) * G3_ + g * H_ + jbase;
            float4 v0 = __ldg((const float4*)src);
            float4 v1 = __ldg((const float4*)(src + 4));
            *(float4*)&sXg[(b * 3 + g) * 8]     = v0;
            *(float4*)&sXg[(b * 3 + g) * 8 + 4] = v1;
        }
        if (tid < 64) {
            const float* src = hprev + (size_t)tid * H_ + jbase;
            float4 v0 = *(const float4*)src;
            float4 v1 = *(const float4*)(src + 4);
            *(float4*)&sHold[tid * 8]     = v0;
            *(float4*)&sHold[tid * 8 + 4] = v1;
        }
        {
            const float* srcb = hprev;
#pragma unroll
            for (int q = 0; q < 8; q++) {
                int i = tid + 256 * q;
                int row = i >> 8, col4 = i & 255;
                cp_async16(sact_base + (uint32_t)((row * 1024 + col4 * 4) * 4),
                           srcb + (size_t)row * H_ + col4 * 4);
            }
            cp_commit();
        }

        for (int r = 0; r < 8; r++) {
            cp_wait0();
            __syncthreads();
            if (r + 1 < 8) {
                const float* srcb = hprev + (size_t)(r + 1) * 8 * H_;
                uint32_t dstb = sact_base + (uint32_t)((((r + 1) & 1) * 8192) * 4);
#pragma unroll
                for (int q = 0; q < 8; q++) {
                    int i = tid + 256 * q;
                    int row = i >> 8, col4 = i & 255;
                    cp_async16(dstb + (uint32_t)((row * 1024 + col4 * 4) * 4),
                               srcb + (size_t)row * H_ + col4 * 4);
                }
                cp_commit();
            }

            float2 acc[8][3];
#pragma unroll
            for (int b = 0; b < 8; b++)
#pragma unroll
                for (int g = 0; g < 3; g++) acc[b][g] = make_float2(0.f, 0.f);

            const float* base = sAct + (r & 1) * 8192 + kg * 32;
#pragma unroll
            for (int kk4 = 0; kk4 < 8; kk4++) {
#pragma unroll
                for (int b = 0; b < 8; b++) {
                    float4 av = *(const float4*)(base + b * 1024 + kk4 * 4);
                    float2 alo2 = make_float2(av.x, av.y);
                    float2 ahi2 = make_float2(av.z, av.w);
#pragma unroll
                    for (int g = 0; g < 3; g++) {
                        acc[b][g] = ffma2(alo2, w[g][2 * kk4],     acc[b][g]);
                        acc[b][g] = ffma2(ahi2, w[g][2 * kk4 + 1], acc[b][g]);
                    }
                }
            }

#pragma unroll
            for (int b = 0; b < 8; b++)
#pragma unroll
                for (int g = 0; g < 3; g++) {
                    float v = acc[b][g].x + acc[b][g].y;
                    v += __shfl_xor_sync(0xffffffffu, v, 8);
                    if ((kg & 1) == 0)
                        sPart[((b * 8 + u) * 3 + g) * 17 + (kg >> 1)] = v;
                }
            __syncthreads();

            if (tid < 64) {
                int b8 = tid >> 3, u2 = tid & 7;
                const float* pp = &sPart[((b8 * 8 + u2) * 3) * 17];
                float s0 = 0.f, s1 = 0.f, s2 = 0.f;
#pragma unroll
                for (int kk = 0; kk < 16; kk++) {
                    s0 += pp[kk];
                    s1 += pp[17 + kk];
                    s2 += pp[34 + kk];
                }
                int b = 8 * r + b8;
                float xr = sXg[(b * 3 + 0) * 8 + u2];
                float xz = sXg[(b * 3 + 1) * 8 + u2];
                float xn = sXg[(b * 3 + 2) * 8 + u2];
                float rr = fast_sigmoid(xr + s0 + sBh[u2]);
                float zz = fast_sigmoid(xz + s1 + sBh[8 + u2]);
                float nn = fast_tanh(xn + rr * (s2 + sBh[16 + u2]));
                float hold = sHold[b * 8 + u2];
                float hnew = (1.0f - zz) * nn + zz * hold;
                int jj = jbase + u2;
                size_t row = (size_t)b * T_ + t;
                hnext[(size_t)b * H_ + jj] = hnew;
                hout[row * H_ + jj] = hnew;
                // fused bf16 hi/lo split for next layer's GEMM A
                __nv_bfloat16 hh = __float2bfloat16_rn(hnew);
                ahi[row * H_ + jj] = hh;
                alo[row * H_ + jj] = __float2bfloat16_rn(hnew - __bfloat162float(hh));
                if (t == T_ - 1) state_out[(size_t)b * H_ + jj] = hnew;
            }
        }
        grid_barrier(c);
    }
}

// ---------------- launch ----------------
extern "C" void kernel_launch(void* const* d_in, const int* in_sizes, int n_in,
                              void* d_out, int out_size)
{
    const void*  x   = d_in[0];
    const float* emb = (const float*)d_in[1];
    const float* Wx0 = (const float*)d_in[2];
    const float* Wh0 = (const float*)d_in[3];
    const float* bx0 = (const float*)d_in[4];
    const float* bh0 = (const float*)d_in[5];
    const float* Wx  = (const float*)d_in[6];
    const float* Wh  = (const float*)d_in[7];
    const float* bx  = (const float*)d_in[8];
    const float* bh  = (const float*)d_in[9];

    float* out     = (float*)d_out;
    float* enc_out = out;
    float* states  = out + (size_t)M_ * H_;
    float* mask    = states + (size_t)4 * B_ * H_;

    void *p_xg, *p_b0, *p_ahi, *p_alo, *p_whi, *p_wlo;
    cudaGetSymbolAddress(&p_xg,  g_xg);
    cudaGetSymbolAddress(&p_b0,  g_buf0);
    cudaGetSymbolAddress(&p_ahi, g_ahi);
    cudaGetSymbolAddress(&p_alo, g_alo);
    cudaGetSymbolAddress(&p_whi, g_wthi);
    cudaGetSymbolAddress(&p_wlo, g_wtlo);
    float* xg  = (float*)p_xg;
    float* b0  = (float*)p_b0;
    __nv_bfloat16* ahi = (__nv_bfloat16*)p_ahi;
    __nv_bfloat16* alo = (__nv_bfloat16*)p_alo;
    __nv_bfloat16* whi = (__nv_bfloat16*)p_whi;
    __nv_bfloat16* wlo = (__nv_bfloat16*)p_wlo;

    cudaFuncSetAttribute(scan_kernel, cudaFuncAttributeMaxDynamicSharedMemorySize,
                         SC_SMEM_BYTES);
    cudaFuncSetAttribute(gemm_mma_kernel, cudaFuncAttributeMaxDynamicSharedMemorySize,
                         GT_SMEM);

    detect_kernel<<<1, 64>>>((const int*)x);
    embed_kernel<<<M_, 128>>>(x, emb, ahi, alo, mask);

    // layer 0: E=512 -> H
    convertWT_kernel<<<dim3(G3_ / 32, E_ / 32), 256>>>(Wx0, whi, wlo, E_);
    gemm_mma_kernel<<<dim3(G3_ / 128, M_ / 128), 256, GT_SMEM>>>(
        ahi, alo, whi, wlo, bx0, xg, E_);
    scan_kernel<<<SC_CTAS, SC_THREADS, SC_SMEM_BYTES>>>(
        xg, Wh0, bh0, b0, ahi, alo, states);

    // layers 1..3: H -> H
    for (int l = 0; l < 3; l++) {
        float* out_act = (l == 2) ? enc_out : b0;
        convertWT_kernel<<<dim3(G3_ / 32, H_ / 32), 256>>>(
            Wx + (size_t)l * H_ * G3_, whi, wlo, H_);
        gemm_mma_kernel<<<dim3(G3_ / 128, M_ / 128), 256, GT_SMEM>>>(
            ahi, alo, whi, wlo, bx + (size_t)l * G3_, xg, H_);
        scan_kernel<<<SC_CTAS, SC_THREADS, SC_SMEM_BYTES>>>(
            xg, Wh + (size_t)l * H_ * G3_, bh + (size_t)l * G3_,
            out_act, ahi, alo, states + (size_t)(l + 1) * B_ * H_);
    }
}

// round 9
// speedup vs baseline: 1.8889x; 1.0521x over previous
#include <cuda_runtime.h>
#include <cuda_bf16.h>
#include <cstdint>
#include <cmath>

#define B_  64
#define T_  512
#define E_  512
#define H_  1024
#define M_  (B_*T_)     // 32768 rows
#define G3_ (3*H_)      // 3072

extern __shared__ char hx_smem[];

// ---------------- scratch ----------------
__device__ float g_xg [(size_t)M_ * G3_];
__device__ float g_buf0[(size_t)M_ * H_];
__device__ float g_h[2][B_ * H_];
__device__ __nv_bfloat16 g_ahi[(size_t)M_ * H_];
__device__ __nv_bfloat16 g_alo[(size_t)M_ * H_];
__device__ __nv_bfloat16 g_wthi[(size_t)G3_ * H_]; // W^T [N][K]
__device__ __nv_bfloat16 g_wtlo[(size_t)G3_ * H_];
__device__ unsigned g_grp_cnt[8];
__device__ unsigned g_root_cnt = 0;
__device__ unsigned g_bar_gen  = 0;
__device__ int g_x_is_i64 = 1;

// ---------------- helpers ----------------
union F2U64 { float2 f2; unsigned long long u; };
__device__ __forceinline__ float2 ffma2(float2 a, float2 b, float2 c) {
    F2U64 A, Bv, C, D;
    A.f2 = a; Bv.f2 = b; C.f2 = c;
    asm("fma.rn.f32x2 %0, %1, %2, %3;" : "=l"(D.u) : "l"(A.u), "l"(Bv.u), "l"(C.u));
    return D.f2;
}
__device__ __forceinline__ float fast_tanh(float x) {
    float y; asm("tanh.approx.f32 %0, %1;" : "=f"(y) : "f"(x)); return y;
}
__device__ __forceinline__ float fast_sigmoid(float x) {
    return 0.5f * fast_tanh(0.5f * x) + 0.5f;
}
__device__ __forceinline__ uint32_t smem_u32(const void* p) {
    return (uint32_t)__cvta_generic_to_shared(p);
}
__device__ __forceinline__ void cp_async16(uint32_t smem_addr, const void* gptr) {
    asm volatile("cp.async.cg.shared.global [%0], [%1], 16;"
                 :: "r"(smem_addr), "l"(gptr));
}
__device__ __forceinline__ void cp_commit() { asm volatile("cp.async.commit_group;"); }
__device__ __forceinline__ void cp_wait0() { asm volatile("cp.async.wait_group 0;"); }
__device__ __forceinline__ void cp_wait1() { asm volatile("cp.async.wait_group 1;"); }

#define LDSM_X4(r, addr) \
    asm volatile("ldmatrix.sync.aligned.m8n8.x4.shared.b16 {%0,%1,%2,%3}, [%4];" \
        : "=r"((r)[0]), "=r"((r)[1]), "=r"((r)[2]), "=r"((r)[3]) : "r"(addr))

#define MMA16816(d, a, b0, b1) \
    asm volatile("mma.sync.aligned.m16n8k16.row.col.f32.bf16.bf16.f32 " \
        "{%0,%1,%2,%3}, {%4,%5,%6,%7}, {%8,%9}, {%0,%1,%2,%3};" \
        : "+f"((d)[0]), "+f"((d)[1]), "+f"((d)[2]), "+f"((d)[3]) \
        : "r"((a)[0]), "r"((a)[1]), "r"((a)[2]), "r"((a)[3]), "r"(b0), "r"(b1))

// ---------------- int64-vs-int32 detection ----------------
__global__ void detect_kernel(const int* __restrict__ x32) {
    __shared__ int nz;
    if (threadIdx.x == 0) nz = 0;
    __syncthreads();
    if (x32[2 * threadIdx.x + 1] != 0) atomicExch(&nz, 1);
    __syncthreads();
    if (threadIdx.x == 0) g_x_is_i64 = (nz == 0) ? 1 : 0;
}

// ---------------- embedding gather (direct bf16 hi/lo) + pad mask ----------------
__global__ __launch_bounds__(128) void embed_kernel(
    const void* __restrict__ xraw, const float* __restrict__ emb,
    __nv_bfloat16* __restrict__ ahi, __nv_bfloat16* __restrict__ alo,
    float* __restrict__ mask_out)
{
    const int r = blockIdx.x;
    long long idx;
    if (g_x_is_i64) idx = ((const long long*)xraw)[r];
    else            idx = (long long)((const int*)xraw)[r];
    float4 v = ((const float4*)(emb + (size_t)idx * E_))[threadIdx.x];
    union { __nv_bfloat16 b[4]; uint2 u; } Hh, Ll;
    float f[4] = {v.x, v.y, v.z, v.w};
#pragma unroll
    for (int q = 0; q < 4; q++) {
        __nv_bfloat16 h = __float2bfloat16_rn(f[q]);
        Hh.b[q] = h;
        Ll.b[q] = __float2bfloat16_rn(f[q] - __bfloat162float(h));
    }
    ((uint2*)(ahi + (size_t)r * E_))[threadIdx.x] = Hh.u;
    ((uint2*)(alo + (size_t)r * E_))[threadIdx.x] = Ll.u;
    if (threadIdx.x == 0) mask_out[r] = (idx != 0) ? 1.0f : 0.0f;
}

// ---------------- W [K][3072] fp32 -> W^T [3072][K] bf16 hi/lo ----------------
__global__ __launch_bounds__(256) void convertWT_kernel(
    const float* __restrict__ W, __nv_bfloat16* __restrict__ Thi,
    __nv_bfloat16* __restrict__ Tlo, int K)
{
    __shared__ float t[32][33];
    const int n0 = blockIdx.x * 32, k0 = blockIdx.y * 32;
    const int tx = threadIdx.x & 31, ty = threadIdx.x >> 5;
#pragma unroll
    for (int i = 0; i < 32; i += 8)
        t[ty + i][tx] = W[(size_t)(k0 + ty + i) * G3_ + n0 + tx];
    __syncthreads();
#pragma unroll
    for (int i = 0; i < 32; i += 8) {
        float v = t[tx][ty + i];
        __nv_bfloat16 h = __float2bfloat16_rn(v);
        size_t o = (size_t)(n0 + ty + i) * K + k0 + tx;
        Thi[o] = h;
        Tlo[o] = __float2bfloat16_rn(v - __bfloat162float(h));
    }
}

// ---------------- bf16-split mma.sync GEMM (unchanged from R8) -------
#define GT_TILE   18432                // 128 * 144
#define GT_STAGE  (4 * GT_TILE)
#define GT_SMEM   (2 * GT_STAGE)       // 147456 B

__global__ __launch_bounds__(256, 1) void gemm_mma_kernel(
    const __nv_bfloat16* __restrict__ Ahi, const __nv_bfloat16* __restrict__ Alo,
    const __nv_bfloat16* __restrict__ Bhi, const __nv_bfloat16* __restrict__ Blo,
    const float* __restrict__ bias, float* __restrict__ C, int K)
{
    const uint32_t sb = smem_u32(hx_smem);
    const int tid = threadIdx.x;
    const int wid = tid >> 5, lid = tid & 31;
    const int wm = wid & 1, wn = wid >> 1;
    const int n0 = blockIdx.x * 128, m0 = blockIdx.y * 128;
    const int nch = K >> 6;

    float acc[4][4][4];
#pragma unroll
    for (int mf = 0; mf < 4; mf++)
#pragma unroll
        for (int n8 = 0; n8 < 4; n8++)
#pragma unroll
            for (int q = 0; q < 4; q++) acc[mf][n8][q] = 0.0f;

    auto stage = [&](int kc) {
        const uint32_t st = sb + (uint32_t)(kc & 1) * GT_STAGE;
        const int koff = kc * 64;
#pragma unroll
        for (int q = 0; q < 4; q++) {
            int i = tid + 256 * q;
            int row = i >> 3, seg = i & 7;
            uint32_t d = st + (uint32_t)(row * 144 + seg * 16);
            size_t ao = (size_t)(m0 + row) * K + koff + seg * 8;
            size_t bo = (size_t)(n0 + row) * K + koff + seg * 8;
            cp_async16(d,               Ahi + ao);
            cp_async16(d + GT_TILE,     Alo + ao);
            cp_async16(d + 2 * GT_TILE, Bhi + bo);
            cp_async16(d + 3 * GT_TILE, Blo + bo);
        }
        cp_commit();
    };

    const int a_row = wm * 64 + (lid & 15);
    const int a_colb = (lid >> 4) * 16;
    const int b_row = wn * 32 + ((lid >> 4) << 3) + (lid & 7);
    const int b_colb = ((lid >> 3) & 1) * 16;

    stage(0);
    for (int c = 0; c < nch; c++) {
        if (c + 1 < nch) { stage(c + 1); cp_wait1(); }
        else             { cp_wait0(); }
        __syncthreads();

        const uint32_t st = sb + (uint32_t)(c & 1) * GT_STAGE;
#pragma unroll
        for (int ks = 0; ks < 4; ks++) {
            const int kb = ks * 32;
            uint32_t ah[4][4], al[4][4], bh[2][4], bl[2][4];
#pragma unroll
            for (int mf = 0; mf < 4; mf++) {
                uint32_t addr = st + (uint32_t)((a_row + mf * 16) * 144 + kb + a_colb);
                LDSM_X4(ah[mf], addr);
                LDSM_X4(al[mf], addr + GT_TILE);
            }
#pragma unroll
            for (int nf = 0; nf < 2; nf++) {
                uint32_t addr = st + 2 * GT_TILE +
                                (uint32_t)((b_row + nf * 16) * 144 + kb + b_colb);
                LDSM_X4(bh[nf], addr);
                LDSM_X4(bl[nf], addr + GT_TILE);
            }
#pragma unroll
            for (int mf = 0; mf < 4; mf++)
#pragma unroll
                for (int n8 = 0; n8 < 4; n8++) {
                    const int nf = n8 >> 1, hh = (n8 & 1) * 2;
                    MMA16816(acc[mf][n8], ah[mf], bh[nf][hh], bh[nf][hh + 1]);
                    MMA16816(acc[mf][n8], ah[mf], bl[nf][hh], bl[nf][hh + 1]);
                    MMA16816(acc[mf][n8], al[mf], bh[nf][hh], bh[nf][hh + 1]);
                }
        }
        __syncthreads();
    }

#pragma unroll
    for (int mf = 0; mf < 4; mf++) {
        const int gm = m0 + wm * 64 + mf * 16 + (lid >> 2);
#pragma unroll
        for (int n8 = 0; n8 < 4; n8++) {
            const int gc = n0 + wn * 32 + n8 * 8 + (lid & 3) * 2;
            float2 bb = *(const float2*)(bias + gc);
            float2 v0, v1;
            v0.x = acc[mf][n8][0] + bb.x; v0.y = acc[mf][n8][1] + bb.y;
            v1.x = acc[mf][n8][2] + bb.x; v1.y = acc[mf][n8][3] + bb.y;
            *(float2*)(C + (size_t)gm * G3_ + gc)       = v0;
            *(float2*)(C + (size_t)(gm + 8) * G3_ + gc) = v1;
        }
    }
}

// ---------------- persistent GRU scan v2 ----------------
// Changes vs R8: (1) XOR-swizzled h staging (kills 4-way LDS bank conflict),
// (2) deferred single-pass stage-2 (full-step partials; one sync; 512 items
// balanced over 256 threads), (3) spin-wait grid barrier (no nanosleep).
#define SC_CTAS    128
#define SC_THREADS 256
#define SA_ACT   0                                // [2][8][1024] swizzled
#define SA_PART  (SA_ACT + 2*8*1024)              // [64][8][3] x 17
#define SA_XG    (SA_PART + 64*8*3*17)
#define SA_HOLD  (SA_XG + 64*3*8)
#define SA_BH    (SA_HOLD + 64*8)
#define SC_SMEM_FLOATS (SA_BH + 24)
#define SC_SMEM_BYTES  (SC_SMEM_FLOATS * 4)       // ~178 KB

__device__ __forceinline__ void grid_barrier(int c) {
    __syncthreads();
    if (threadIdx.x == 0) {
        __threadfence();
        unsigned gen = *(volatile unsigned*)&g_bar_gen;
        int grp = c & 7;
        if (atomicAdd(&g_grp_cnt[grp], 1u) == 15u) {
            if (atomicAdd(&g_root_cnt, 1u) == 7u) {
                atomicExch(&g_root_cnt, 0u);
#pragma unroll
                for (int i = 0; i < 8; i++) atomicExch(&g_grp_cnt[i], 0u);
                __threadfence();
                atomicAdd(&g_bar_gen, 1u);
            }
        }
        while (*(volatile unsigned*)&g_bar_gen == gen) { }
        __threadfence();
    }
    __syncthreads();
}

__global__ __launch_bounds__(SC_THREADS, 1) void scan_kernel(
    const float* __restrict__ xg, const float* __restrict__ Wh,
    const float* __restrict__ bh, float* __restrict__ hout,
    __nv_bfloat16* __restrict__ ahi, __nv_bfloat16* __restrict__ alo,
    float* __restrict__ state_out)
{
    float* smem  = (float*)hx_smem;
    float* sAct  = smem + SA_ACT;
    float* sPart = smem + SA_PART;
    float* sXg   = smem + SA_XG;
    float* sHold = smem + SA_HOLD;
    float* sBh   = smem + SA_BH;

    const int c   = blockIdx.x;
    const int tid = threadIdx.x;
    const int u   = tid & 7;
    const int kg  = tid >> 3;          // 0..31
    const int jbase = c * 8;
    const int j   = jbase + u;
    const int sw  = kg & 7;            // swizzle key

    // weights in registers for the whole scan
    float2 w[3][16];
    {
        const int kbase = kg * 32;
#pragma unroll
        for (int g = 0; g < 3; g++)
#pragma unroll
            for (int kk2 = 0; kk2 < 16; kk2++) {
                int k = kbase + 2 * kk2;
                w[g][kk2].x = __ldg(Wh + (size_t)k       * G3_ + g * H_ + j);
                w[g][kk2].y = __ldg(Wh + (size_t)(k + 1) * G3_ + g * H_ + j);
            }
    }
    if (tid < 24) sBh[tid] = bh[(tid >> 3) * H_ + jbase + (tid & 7)];
    for (int i = tid; i < B_ * 8; i += SC_THREADS) {
        int b = i >> 3, uu = i & 7;
        g_h[0][b * H_ + jbase + uu] = 0.0f;
    }
    grid_barrier(c);

    const uint32_t sact_base = smem_u32(sAct);

    for (int t = 0; t < T_; t++) {
        const float* hprev = g_h[t & 1];
        float*       hnext = g_h[(t + 1) & 1];

        // prefetch this step's xg and hold into smem (latency hidden by rounds)
        if (tid < 192) {
            int b = tid / 3, g = tid - 3 * b;
            const float* src = xg + ((size_t)b * T_ + t) * G3_ + g * H_ + jbase;
            float4 v0 = __ldg((const float4*)src);
            float4 v1 = __ldg((const float4*)(src + 4));
            *(float4*)&sXg[(b * 3 + g) * 8]     = v0;
            *(float4*)&sXg[(b * 3 + g) * 8 + 4] = v1;
        }
        if (tid < 64) {
            const float* src = hprev + (size_t)tid * H_ + jbase;
            float4 v0 = *(const float4*)src;
            float4 v1 = *(const float4*)(src + 4);
            *(float4*)&sHold[tid * 8]     = v0;
            *(float4*)&sHold[tid * 8 + 4] = v1;
        }
        // kick round 0 staging (swizzled)
        {
            const float* srcb = hprev;
#pragma unroll
            for (int q = 0; q < 8; q++) {
                int i = tid + 256 * q;
                int row = i >> 8, col4 = i & 255;
                int phys = col4 ^ ((col4 >> 3) & 7);
                cp_async16(sact_base + (uint32_t)((row * 1024 + phys * 4) * 4),
                           srcb + (size_t)row * H_ + col4 * 4);
            }
            cp_commit();
        }

        for (int r = 0; r < 8; r++) {
            cp_wait0();
            __syncthreads();
            if (r + 1 < 8) {
                const float* srcb = hprev + (size_t)(r + 1) * 8 * H_;
                uint32_t dstb = sact_base + (uint32_t)((((r + 1) & 1) * 8192) * 4);
#pragma unroll
                for (int q = 0; q < 8; q++) {
                    int i = tid + 256 * q;
                    int row = i >> 8, col4 = i & 255;
                    int phys = col4 ^ ((col4 >> 3) & 7);
                    cp_async16(dstb + (uint32_t)((row * 1024 + phys * 4) * 4),
                               srcb + (size_t)row * H_ + col4 * 4);
                }
                cp_commit();
            }

            float2 acc[8][3];
#pragma unroll
            for (int b = 0; b < 8; b++)
#pragma unroll
                for (int g = 0; g < 3; g++) acc[b][g] = make_float2(0.f, 0.f);

            // swizzled reads: logical unit kg*8+kk4 lives at physical offset
            // kg*32 + (kk4^sw)*4 floats
            const float* bufb = sAct + (r & 1) * 8192 + kg * 32;
#pragma unroll
            for (int kk4 = 0; kk4 < 8; kk4++) {
                const int po = (kk4 ^ sw) * 4;
#pragma unroll
                for (int b = 0; b < 8; b++) {
                    float4 av = *(const float4*)(bufb + b * 1024 + po);
                    float2 alo2 = make_float2(av.x, av.y);
                    float2 ahi2 = make_float2(av.z, av.w);
#pragma unroll
                    for (int g = 0; g < 3; g++) {
                        acc[b][g] = ffma2(alo2, w[g][2 * kk4],     acc[b][g]);
                        acc[b][g] = ffma2(ahi2, w[g][2 * kk4 + 1], acc[b][g]);
                    }
                }
            }

            // reduce to 16 partials per (b,g,u); store into full-step sPart
#pragma unroll
            for (int b = 0; b < 8; b++)
#pragma unroll
                for (int g = 0; g < 3; g++) {
                    float v = acc[b][g].x + acc[b][g].y;
                    v += __shfl_xor_sync(0xffffffffu, v, 8);
                    if ((kg & 1) == 0)
                        sPart[(((r * 8 + b) * 8 + u) * 3 + g) * 17 + (kg >> 1)] = v;
                }
        }
        __syncthreads();

        // single balanced stage-2: 512 (b,u) items over 256 threads
#pragma unroll
        for (int it = 0; it < 2; it++) {
            int item = tid + it * 256;
            int b = item >> 3, u2 = item & 7;
            const float* pp = &sPart[((b * 8 + u2) * 3) * 17];
            float s0 = 0.f, s1 = 0.f, s2 = 0.f;
#pragma unroll
            for (int kk = 0; kk < 16; kk++) {
                s0 += pp[kk];
                s1 += pp[17 + kk];
                s2 += pp[34 + kk];
            }
            float xr = sXg[(b * 3 + 0) * 8 + u2];
            float xz = sXg[(b * 3 + 1) * 8 + u2];
            float xn = sXg[(b * 3 + 2) * 8 + u2];
            float rr = fast_sigmoid(xr + s0 + sBh[u2]);
            float zz = fast_sigmoid(xz + s1 + sBh[8 + u2]);
            float nn = fast_tanh(xn + rr * (s2 + sBh[16 + u2]));
            float hold = sHold[b * 8 + u2];
            float hnew = (1.0f - zz) * nn + zz * hold;
            int jj = jbase + u2;
            size_t row = (size_t)b * T_ + t;
            hnext[(size_t)b * H_ + jj] = hnew;
            hout[row * H_ + jj] = hnew;
            __nv_bfloat16 hh = __float2bfloat16_rn(hnew);
            ahi[row * H_ + jj] = hh;
            alo[row * H_ + jj] = __float2bfloat16_rn(hnew - __bfloat162float(hh));
            if (t == T_ - 1) state_out[(size_t)b * H_ + jj] = hnew;
        }
        grid_barrier(c);
    }
}

// ---------------- launch ----------------
extern "C" void kernel_launch(void* const* d_in, const int* in_sizes, int n_in,
                              void* d_out, int out_size)
{
    const void*  x   = d_in[0];
    const float* emb = (const float*)d_in[1];
    const float* Wx0 = (const float*)d_in[2];
    const float* Wh0 = (const float*)d_in[3];
    const float* bx0 = (const float*)d_in[4];
    const float* bh0 = (const float*)d_in[5];
    const float* Wx  = (const float*)d_in[6];
    const float* Wh  = (const float*)d_in[7];
    const float* bx  = (const float*)d_in[8];
    const float* bh  = (const float*)d_in[9];

    float* out     = (float*)d_out;
    float* enc_out = out;
    float* states  = out + (size_t)M_ * H_;
    float* mask    = states + (size_t)4 * B_ * H_;

    void *p_xg, *p_b0, *p_ahi, *p_alo, *p_whi, *p_wlo;
    cudaGetSymbolAddress(&p_xg,  g_xg);
    cudaGetSymbolAddress(&p_b0,  g_buf0);
    cudaGetSymbolAddress(&p_ahi, g_ahi);
    cudaGetSymbolAddress(&p_alo, g_alo);
    cudaGetSymbolAddress(&p_whi, g_wthi);
    cudaGetSymbolAddress(&p_wlo, g_wtlo);
    float* xg  = (float*)p_xg;
    float* b0  = (float*)p_b0;
    __nv_bfloat16* ahi = (__nv_bfloat16*)p_ahi;
    __nv_bfloat16* alo = (__nv_bfloat16*)p_alo;
    __nv_bfloat16* whi = (__nv_bfloat16*)p_whi;
    __nv_bfloat16* wlo = (__nv_bfloat16*)p_wlo;

    cudaFuncSetAttribute(scan_kernel, cudaFuncAttributeMaxDynamicSharedMemorySize,
                         SC_SMEM_BYTES);
    cudaFuncSetAttribute(gemm_mma_kernel, cudaFuncAttributeMaxDynamicSharedMemorySize,
                         GT_SMEM);

    detect_kernel<<<1, 64>>>((const int*)x);
    embed_kernel<<<M_, 128>>>(x, emb, ahi, alo, mask);

    // layer 0: E=512 -> H
    convertWT_kernel<<<dim3(G3_ / 32, E_ / 32), 256>>>(Wx0, whi, wlo, E_);
    gemm_mma_kernel<<<dim3(G3_ / 128, M_ / 128), 256, GT_SMEM>>>(
        ahi, alo, whi, wlo, bx0, xg, E_);
    scan_kernel<<<SC_CTAS, SC_THREADS, SC_SMEM_BYTES>>>(
        xg, Wh0, bh0, b0, ahi, alo, states);

    // layers 1..3: H -> H
    for (int l = 0; l < 3; l++) {
        float* out_act = (l == 2) ? enc_out : b0;
        convertWT_kernel<<<dim3(G3_ / 32, H_ / 32), 256>>>(
            Wx + (size_t)l * H_ * G3_, whi, wlo, H_);
        gemm_mma_kernel<<<dim3(G3_ / 128, M_ / 128), 256, GT_SMEM>>>(
            ahi, alo, whi, wlo, bx + (size_t)l * G3_, xg, H_);
        scan_kernel<<<SC_CTAS, SC_THREADS, SC_SMEM_BYTES>>>(
            xg, Wh + (size_t)l * H_ * G3_, bh + (size_t)l * G3_,
            out_act, ahi, alo, states + (size_t)(l + 1) * B_ * H_);
    }
}

// round 10
// speedup vs baseline: 1.8893x; 1.0002x over previous
#include <cuda_runtime.h>
#include <cuda_bf16.h>
#include <cstdint>
#include <cmath>

#define B_  64
#define T_  512
#define E_  512
#define H_  1024
#define M_  (B_*T_)     // 32768 rows
#define G3_ (3*H_)      // 3072

extern __shared__ char hx_smem[];

// ---------------- scratch ----------------
__device__ float g_xg [(size_t)M_ * G3_];
__device__ float g_buf0[(size_t)M_ * H_];
__device__ float g_h[2][B_ * H_];
__device__ __nv_bfloat16 g_ahi[(size_t)M_ * H_];
__device__ __nv_bfloat16 g_alo[(size_t)M_ * H_];
__device__ __nv_bfloat16 g_wthi[(size_t)G3_ * H_]; // W^T [N][K]
__device__ __nv_bfloat16 g_wtlo[(size_t)G3_ * H_];
__device__ unsigned g_grp_cnt[8];
__device__ unsigned g_root_cnt = 0;
__device__ unsigned g_bar_gen  = 0;
__device__ int g_x_is_i64 = 1;

// ---------------- helpers ----------------
union F2U64 { float2 f2; unsigned long long u; };
__device__ __forceinline__ float2 ffma2(float2 a, float2 b, float2 c) {
    F2U64 A, Bv, C, D;
    A.f2 = a; Bv.f2 = b; C.f2 = c;
    asm("fma.rn.f32x2 %0, %1, %2, %3;" : "=l"(D.u) : "l"(A.u), "l"(Bv.u), "l"(C.u));
    return D.f2;
}
__device__ __forceinline__ float fast_tanh(float x) {
    float y; asm("tanh.approx.f32 %0, %1;" : "=f"(y) : "f"(x)); return y;
}
__device__ __forceinline__ float fast_sigmoid(float x) {
    return 0.5f * fast_tanh(0.5f * x) + 0.5f;
}
__device__ __forceinline__ uint32_t smem_u32(const void* p) {
    return (uint32_t)__cvta_generic_to_shared(p);
}
__device__ __forceinline__ void cp_async16(uint32_t smem_addr, const void* gptr) {
    asm volatile("cp.async.cg.shared.global [%0], [%1], 16;"
                 :: "r"(smem_addr), "l"(gptr));
}
__device__ __forceinline__ void cp_commit() { asm volatile("cp.async.commit_group;"); }
__device__ __forceinline__ void cp_wait0() { asm volatile("cp.async.wait_group 0;"); }
__device__ __forceinline__ void cp_wait1() { asm volatile("cp.async.wait_group 1;"); }

#define LDSM_X4(r, addr) \
    asm volatile("ldmatrix.sync.aligned.m8n8.x4.shared.b16 {%0,%1,%2,%3}, [%4];" \
        : "=r"((r)[0]), "=r"((r)[1]), "=r"((r)[2]), "=r"((r)[3]) : "r"(addr))

#define MMA16816(d, a, b0, b1) \
    asm volatile("mma.sync.aligned.m16n8k16.row.col.f32.bf16.bf16.f32 " \
        "{%0,%1,%2,%3}, {%4,%5,%6,%7}, {%8,%9}, {%0,%1,%2,%3};" \
        : "+f"((d)[0]), "+f"((d)[1]), "+f"((d)[2]), "+f"((d)[3]) \
        : "r"((a)[0]), "r"((a)[1]), "r"((a)[2]), "r"((a)[3]), "r"(b0), "r"(b1))

// ---------------- int64-vs-int32 detection ----------------
__global__ void detect_kernel(const int* __restrict__ x32) {
    __shared__ int nz;
    if (threadIdx.x == 0) nz = 0;
    __syncthreads();
    if (x32[2 * threadIdx.x + 1] != 0) atomicExch(&nz, 1);
    __syncthreads();
    if (threadIdx.x == 0) g_x_is_i64 = (nz == 0) ? 1 : 0;
}

// ---------------- embedding gather (direct bf16 hi/lo) + pad mask ----------------
__global__ __launch_bounds__(128) void embed_kernel(
    const void* __restrict__ xraw, const float* __restrict__ emb,
    __nv_bfloat16* __restrict__ ahi, __nv_bfloat16* __restrict__ alo,
    float* __restrict__ mask_out)
{
    const int r = blockIdx.x;
    long long idx;
    if (g_x_is_i64) idx = ((const long long*)xraw)[r];
    else            idx = (long long)((const int*)xraw)[r];
    float4 v = ((const float4*)(emb + (size_t)idx * E_))[threadIdx.x];
    union { __nv_bfloat16 b[4]; uint2 u; } Hh, Ll;
    float f[4] = {v.x, v.y, v.z, v.w};
#pragma unroll
    for (int q = 0; q < 4; q++) {
        __nv_bfloat16 h = __float2bfloat16_rn(f[q]);
        Hh.b[q] = h;
        Ll.b[q] = __float2bfloat16_rn(f[q] - __bfloat162float(h));
    }
    ((uint2*)(ahi + (size_t)r * E_))[threadIdx.x] = Hh.u;
    ((uint2*)(alo + (size_t)r * E_))[threadIdx.x] = Ll.u;
    if (threadIdx.x == 0) mask_out[r] = (idx != 0) ? 1.0f : 0.0f;
}

// ---------------- W [K][3072] fp32 -> W^T [3072][K] bf16 hi/lo ----------------
__global__ __launch_bounds__(256) void convertWT_kernel(
    const float* __restrict__ W, __nv_bfloat16* __restrict__ Thi,
    __nv_bfloat16* __restrict__ Tlo, int K)
{
    __shared__ float t[32][33];
    const int n0 = blockIdx.x * 32, k0 = blockIdx.y * 32;
    const int tx = threadIdx.x & 31, ty = threadIdx.x >> 5;
#pragma unroll
    for (int i = 0; i < 32; i += 8)
        t[ty + i][tx] = W[(size_t)(k0 + ty + i) * G3_ + n0 + tx];
    __syncthreads();
#pragma unroll
    for (int i = 0; i < 32; i += 8) {
        float v = t[tx][ty + i];
        __nv_bfloat16 h = __float2bfloat16_rn(v);
        size_t o = (size_t)(n0 + ty + i) * K + k0 + tx;
        Thi[o] = h;
        Tlo[o] = __float2bfloat16_rn(v - __bfloat162float(h));
    }
}

// ---------------- bf16-split mma.sync GEMM (unchanged from R9) -------
#define GT_TILE   18432                // 128 * 144
#define GT_STAGE  (4 * GT_TILE)
#define GT_SMEM   (2 * GT_STAGE)       // 147456 B

__global__ __launch_bounds__(256, 1) void gemm_mma_kernel(
    const __nv_bfloat16* __restrict__ Ahi, const __nv_bfloat16* __restrict__ Alo,
    const __nv_bfloat16* __restrict__ Bhi, const __nv_bfloat16* __restrict__ Blo,
    const float* __restrict__ bias, float* __restrict__ C, int K)
{
    const uint32_t sb = smem_u32(hx_smem);
    const int tid = threadIdx.x;
    const int wid = tid >> 5, lid = tid & 31;
    const int wm = wid & 1, wn = wid >> 1;
    const int n0 = blockIdx.x * 128, m0 = blockIdx.y * 128;
    const int nch = K >> 6;

    float acc[4][4][4];
#pragma unroll
    for (int mf = 0; mf < 4; mf++)
#pragma unroll
        for (int n8 = 0; n8 < 4; n8++)
#pragma unroll
            for (int q = 0; q < 4; q++) acc[mf][n8][q] = 0.0f;

    auto stage = [&](int kc) {
        const uint32_t st = sb + (uint32_t)(kc & 1) * GT_STAGE;
        const int koff = kc * 64;
#pragma unroll
        for (int q = 0; q < 4; q++) {
            int i = tid + 256 * q;
            int row = i >> 3, seg = i & 7;
            uint32_t d = st + (uint32_t)(row * 144 + seg * 16);
            size_t ao = (size_t)(m0 + row) * K + koff + seg * 8;
            size_t bo = (size_t)(n0 + row) * K + koff + seg * 8;
            cp_async16(d,               Ahi + ao);
            cp_async16(d + GT_TILE,     Alo + ao);
            cp_async16(d + 2 * GT_TILE, Bhi + bo);
            cp_async16(d + 3 * GT_TILE, Blo + bo);
        }
        cp_commit();
    };

    const int a_row = wm * 64 + (lid & 15);
    const int a_colb = (lid >> 4) * 16;
    const int b_row = wn * 32 + ((lid >> 4) << 3) + (lid & 7);
    const int b_colb = ((lid >> 3) & 1) * 16;

    stage(0);
    for (int c = 0; c < nch; c++) {
        if (c + 1 < nch) { stage(c + 1); cp_wait1(); }
        else             { cp_wait0(); }
        __syncthreads();

        const uint32_t st = sb + (uint32_t)(c & 1) * GT_STAGE;
#pragma unroll
        for (int ks = 0; ks < 4; ks++) {
            const int kb = ks * 32;
            uint32_t ah[4][4], al[4][4], bh[2][4], bl[2][4];
#pragma unroll
            for (int mf = 0; mf < 4; mf++) {
                uint32_t addr = st + (uint32_t)((a_row + mf * 16) * 144 + kb + a_colb);
                LDSM_X4(ah[mf], addr);
                LDSM_X4(al[mf], addr + GT_TILE);
            }
#pragma unroll
            for (int nf = 0; nf < 2; nf++) {
                uint32_t addr = st + 2 * GT_TILE +
                                (uint32_t)((b_row + nf * 16) * 144 + kb + b_colb);
                LDSM_X4(bh[nf], addr);
                LDSM_X4(bl[nf], addr + GT_TILE);
            }
#pragma unroll
            for (int mf = 0; mf < 4; mf++)
#pragma unroll
                for (int n8 = 0; n8 < 4; n8++) {
                    const int nf = n8 >> 1, hh = (n8 & 1) * 2;
                    MMA16816(acc[mf][n8], ah[mf], bh[nf][hh], bh[nf][hh + 1]);
                    MMA16816(acc[mf][n8], ah[mf], bl[nf][hh], bl[nf][hh + 1]);
                    MMA16816(acc[mf][n8], al[mf], bh[nf][hh], bh[nf][hh + 1]);
                }
        }
        __syncthreads();
    }

#pragma unroll
    for (int mf = 0; mf < 4; mf++) {
        const int gm = m0 + wm * 64 + mf * 16 + (lid >> 2);
#pragma unroll
        for (int n8 = 0; n8 < 4; n8++) {
            const int gc = n0 + wn * 32 + n8 * 8 + (lid & 3) * 2;
            float2 bb = *(const float2*)(bias + gc);
            float2 v0, v1;
            v0.x = acc[mf][n8][0] + bb.x; v0.y = acc[mf][n8][1] + bb.y;
            v1.x = acc[mf][n8][2] + bb.x; v1.y = acc[mf][n8][3] + bb.y;
            *(float2*)(C + (size_t)gm * G3_ + gc)       = v0;
            *(float2*)(C + (size_t)(gm + 8) * G3_ + gc) = v1;
        }
    }
}

// ---------------- persistent GRU scan v3 ----------------
// vs R9: register double-buffered activation loads (avA/avB b-blocks of 4)
// so every LDS.128 issues >=24 FFMA2s before its first consumer.
#define SC_CTAS    128
#define SC_THREADS 256
#define SA_ACT   0                                // [2][8][1024] swizzled
#define SA_PART  (SA_ACT + 2*8*1024)              // [64][8][3] x 17
#define SA_XG    (SA_PART + 64*8*3*17)
#define SA_HOLD  (SA_XG + 64*3*8)
#define SA_BH    (SA_HOLD + 64*8)
#define SC_SMEM_FLOATS (SA_BH + 24)
#define SC_SMEM_BYTES  (SC_SMEM_FLOATS * 4)       // ~178 KB

__device__ __forceinline__ void grid_barrier(int c) {
    __syncthreads();
    if (threadIdx.x == 0) {
        __threadfence();
        unsigned gen = *(volatile unsigned*)&g_bar_gen;
        int grp = c & 7;
        if (atomicAdd(&g_grp_cnt[grp], 1u) == 15u) {
            if (atomicAdd(&g_root_cnt, 1u) == 7u) {
                atomicExch(&g_root_cnt, 0u);
#pragma unroll
                for (int i = 0; i < 8; i++) atomicExch(&g_grp_cnt[i], 0u);
                __threadfence();
                atomicAdd(&g_bar_gen, 1u);
            }
        }
        while (*(volatile unsigned*)&g_bar_gen == gen) { }
        __threadfence();
    }
    __syncthreads();
}

__global__ __launch_bounds__(SC_THREADS, 1) void scan_kernel(
    const float* __restrict__ xg, const float* __restrict__ Wh,
    const float* __restrict__ bh, float* __restrict__ hout,
    __nv_bfloat16* __restrict__ ahi, __nv_bfloat16* __restrict__ alo,
    float* __restrict__ state_out)
{
    float* smem  = (float*)hx_smem;
    float* sAct  = smem + SA_ACT;
    float* sPart = smem + SA_PART;
    float* sXg   = smem + SA_XG;
    float* sHold = smem + SA_HOLD;
    float* sBh   = smem + SA_BH;

    const int c   = blockIdx.x;
    const int tid = threadIdx.x;
    const int u   = tid & 7;
    const int kg  = tid >> 3;          // 0..31
    const int jbase = c * 8;
    const int j   = jbase + u;
    const int sw  = kg & 7;            // swizzle key

    // weights in registers for the whole scan
    float2 w[3][16];
    {
        const int kbase = kg * 32;
#pragma unroll
        for (int g = 0; g < 3; g++)
#pragma unroll
            for (int kk2 = 0; kk2 < 16; kk2++) {
                int k = kbase + 2 * kk2;
                w[g][kk2].x = __ldg(Wh + (size_t)k       * G3_ + g * H_ + j);
                w[g][kk2].y = __ldg(Wh + (size_t)(k + 1) * G3_ + g * H_ + j);
            }
    }
    if (tid < 24) sBh[tid] = bh[(tid >> 3) * H_ + jbase + (tid & 7)];
    for (int i = tid; i < B_ * 8; i += SC_THREADS) {
        int b = i >> 3, uu = i & 7;
        g_h[0][b * H_ + jbase + uu] = 0.0f;
    }
    grid_barrier(c);

    const uint32_t sact_base = smem_u32(sAct);

    for (int t = 0; t < T_; t++) {
        const float* hprev = g_h[t & 1];
        float*       hnext = g_h[(t + 1) & 1];

        // prefetch this step's xg and hold into smem
        if (tid < 192) {
            int b = tid / 3, g = tid - 3 * b;
            const float* src = xg + ((size_t)b * T_ + t) * G3_ + g * H_ + jbase;
            float4 v0 = __ldg((const float4*)src);
            float4 v1 = __ldg((const float4*)(src + 4));
            *(float4*)&sXg[(b * 3 + g) * 8]     = v0;
            *(float4*)&sXg[(b * 3 + g) * 8 + 4] = v1;
        }
        if (tid < 64) {
            const float* src = hprev + (size_t)tid * H_ + jbase;
            float4 v0 = *(const float4*)src;
            float4 v1 = *(const float4*)(src + 4);
            *(float4*)&sHold[tid * 8]     = v0;
            *(float4*)&sHold[tid * 8 + 4] = v1;
        }
        // kick round 0 staging (swizzled)
        {
            const float* srcb = hprev;
#pragma unroll
            for (int q = 0; q < 8; q++) {
                int i = tid + 256 * q;
                int row = i >> 8, col4 = i & 255;
                int phys = col4 ^ ((col4 >> 3) & 7);
                cp_async16(sact_base + (uint32_t)((row * 1024 + phys * 4) * 4),
                           srcb + (size_t)row * H_ + col4 * 4);
            }
            cp_commit();
        }

        for (int r = 0; r < 8; r++) {
            cp_wait0();
            __syncthreads();
            if (r + 1 < 8) {
                const float* srcb = hprev + (size_t)(r + 1) * 8 * H_;
                uint32_t dstb = sact_base + (uint32_t)((((r + 1) & 1) * 8192) * 4);
#pragma unroll
                for (int q = 0; q < 8; q++) {
                    int i = tid + 256 * q;
                    int row = i >> 8, col4 = i & 255;
                    int phys = col4 ^ ((col4 >> 3) & 7);
                    cp_async16(dstb + (uint32_t)((row * 1024 + phys * 4) * 4),
                               srcb + (size_t)row * H_ + col4 * 4);
                }
                cp_commit();
            }

            float2 acc[8][3];
#pragma unroll
            for (int b = 0; b < 8; b++)
#pragma unroll
                for (int g = 0; g < 3; g++) acc[b][g] = make_float2(0.f, 0.f);

            const float* bufb = sAct + (r & 1) * 8192 + kg * 32;

            // register double-buffered activation pipeline
            float4 avA[4], avB[4];
#pragma unroll
            for (int i = 0; i < 4; i++)
                avA[i] = *(const float4*)(bufb + i * 1024 + sw * 4);   // kk4=0

#pragma unroll
            for (int kk4 = 0; kk4 < 8; kk4++) {
                const int po = (kk4 ^ sw) * 4;
                // prefetch b=4..7 for this kk4
#pragma unroll
                for (int i = 0; i < 4; i++)
                    avB[i] = *(const float4*)(bufb + (i + 4) * 1024 + po);
                // compute b=0..3 with avA
#pragma unroll
                for (int i = 0; i < 4; i++) {
                    float2 lo = make_float2(avA[i].x, avA[i].y);
                    float2 hi = make_float2(avA[i].z, avA[i].w);
#pragma unroll
                    for (int g = 0; g < 3; g++) {
                        acc[i][g] = ffma2(lo, w[g][2 * kk4],     acc[i][g]);
                        acc[i][g] = ffma2(hi, w[g][2 * kk4 + 1], acc[i][g]);
                    }
                }
                // prefetch b=0..3 for next kk4 (wraps harmlessly at kk4=7)
                const int pon = (((kk4 + 1) & 7) ^ sw) * 4;
#pragma unroll
                for (int i = 0; i < 4; i++)
                    avA[i] = *(const float4*)(bufb + i * 1024 + pon);
                // compute b=4..7 with avB
#pragma unroll
                for (int i = 0; i < 4; i++) {
                    float2 lo = make_float2(avB[i].x, avB[i].y);
                    float2 hi = make_float2(avB[i].z, avB[i].w);
#pragma unroll
                    for (int g = 0; g < 3; g++) {
                        acc[i + 4][g] = ffma2(lo, w[g][2 * kk4],     acc[i + 4][g]);
                        acc[i + 4][g] = ffma2(hi, w[g][2 * kk4 + 1], acc[i + 4][g]);
                    }
                }
            }

            // reduce to 16 partials per (b,g,u); store into full-step sPart
#pragma unroll
            for (int b = 0; b < 8; b++)
#pragma unroll
                for (int g = 0; g < 3; g++) {
                    float v = acc[b][g].x + acc[b][g].y;
                    v += __shfl_xor_sync(0xffffffffu, v, 8);
                    if ((kg & 1) == 0)
                        sPart[(((r * 8 + b) * 8 + u) * 3 + g) * 17 + (kg >> 1)] = v;
                }
        }
        __syncthreads();

        // single balanced stage-2: 512 (b,u) items over 256 threads
#pragma unroll
        for (int it = 0; it < 2; it++) {
            int item = tid + it * 256;
            int b = item >> 3, u2 = item & 7;
            const float* pp = &sPart[((b * 8 + u2) * 3) * 17];
            float s0 = 0.f, s1 = 0.f, s2 = 0.f;
#pragma unroll
            for (int kk = 0; kk < 16; kk++) {
                s0 += pp[kk];
                s1 += pp[17 + kk];
                s2 += pp[34 + kk];
            }
            float xr = sXg[(b * 3 + 0) * 8 + u2];
            float xz = sXg[(b * 3 + 1) * 8 + u2];
            float xn = sXg[(b * 3 + 2) * 8 + u2];
            float rr = fast_sigmoid(xr + s0 + sBh[u2]);
            float zz = fast_sigmoid(xz + s1 + sBh[8 + u2]);
            float nn = fast_tanh(xn + rr * (s2 + sBh[16 + u2]));
            float hold = sHold[b * 8 + u2];
            float hnew = (1.0f - zz) * nn + zz * hold;
            int jj = jbase + u2;
            size_t row = (size_t)b * T_ + t;
            hnext[(size_t)b * H_ + jj] = hnew;
            hout[row * H_ + jj] = hnew;
            __nv_bfloat16 hh = __float2bfloat16_rn(hnew);
            ahi[row * H_ + jj] = hh;
            alo[row * H_ + jj] = __float2bfloat16_rn(hnew - __bfloat162float(hh));
            if (t == T_ - 1) state_out[(size_t)b * H_ + jj] = hnew;
        }
        grid_barrier(c);
    }
}

// ---------------- launch ----------------
extern "C" void kernel_launch(void* const* d_in, const int* in_sizes, int n_in,
                              void* d_out, int out_size)
{
    const void*  x   = d_in[0];
    const float* emb = (const float*)d_in[1];
    const float* Wx0 = (const float*)d_in[2];
    const float* Wh0 = (const float*)d_in[3];
    const float* bx0 = (const float*)d_in[4];
    const float* bh0 = (const float*)d_in[5];
    const float* Wx  = (const float*)d_in[6];
    const float* Wh  = (const float*)d_in[7];
    const float* bx  = (const float*)d_in[8];
    const float* bh  = (const float*)d_in[9];

    float* out     = (float*)d_out;
    float* enc_out = out;
    float* states  = out + (size_t)M_ * H_;
    float* mask    = states + (size_t)4 * B_ * H_;

    void *p_xg, *p_b0, *p_ahi, *p_alo, *p_whi, *p_wlo;
    cudaGetSymbolAddress(&p_xg,  g_xg);
    cudaGetSymbolAddress(&p_b0,  g_buf0);
    cudaGetSymbolAddress(&p_ahi, g_ahi);
    cudaGetSymbolAddress(&p_alo, g_alo);
    cudaGetSymbolAddress(&p_whi, g_wthi);
    cudaGetSymbolAddress(&p_wlo, g_wtlo);
    float* xg  = (float*)p_xg;
    float* b0  = (float*)p_b0;
    __nv_bfloat16* ahi = (__nv_bfloat16*)p_ahi;
    __nv_bfloat16* alo = (__nv_bfloat16*)p_alo;
    __nv_bfloat16* whi = (__nv_bfloat16*)p_whi;
    __nv_bfloat16* wlo = (__nv_bfloat16*)p_wlo;

    cudaFuncSetAttribute(scan_kernel, cudaFuncAttributeMaxDynamicSharedMemorySize,
                         SC_SMEM_BYTES);
    cudaFuncSetAttribute(gemm_mma_kernel, cudaFuncAttributeMaxDynamicSharedMemorySize,
                         GT_SMEM);

    detect_kernel<<<1, 64>>>((const int*)x);
    embed_kernel<<<M_, 128>>>(x, emb, ahi, alo, mask);

    // layer 0: E=512 -> H
    convertWT_kernel<<<dim3(G3_ / 32, E_ / 32), 256>>>(Wx0, whi, wlo, E_);
    gemm_mma_kernel<<<dim3(G3_ / 128, M_ / 128), 256, GT_SMEM>>>(
        ahi, alo, whi, wlo, bx0, xg, E_);
    scan_kernel<<<SC_CTAS, SC_THREADS, SC_SMEM_BYTES>>>(
        xg, Wh0, bh0, b0, ahi, alo, states);

    // layers 1..3: H -> H
    for (int l = 0; l < 3; l++) {
        float* out_act = (l == 2) ? enc_out : b0;
        convertWT_kernel<<<dim3(G3_ / 32, H_ / 32), 256>>>(
            Wx + (size_t)l * H_ * G3_, whi, wlo, H_);
        gemm_mma_kernel<<<dim3(G3_ / 128, M_ / 128), 256, GT_SMEM>>>(
            ahi, alo, whi, wlo, bx + (size_t)l * G3_, xg, H_);
        scan_kernel<<<SC_CTAS, SC_THREADS, SC_SMEM_BYTES>>>(
            xg, Wh + (size_t)l * H_ * G3_, bh + (size_t)l * G3_,
            out_act, ahi, alo, states + (size_t)(l + 1) * B_ * H_);
    }
}

// round 11
// speedup vs baseline: 1.9989x; 1.0580x over previous
#include <cuda_runtime.h>
#include <cuda_bf16.h>
#include <cstdint>
#include <cmath>

#define B_  64
#define T_  512
#define E_  512
#define H_  1024
#define M_  (B_*T_)     // 32768 rows
#define G3_ (3*H_)      // 3072

extern __shared__ char hx_smem[];

// ---------------- scratch ----------------
__device__ float g_xg [(size_t)M_ * G3_];
__device__ float g_buf0[(size_t)M_ * H_];
__device__ float g_h[2][B_ * H_];
__device__ float g_gpre[(size_t)B_ * G3_];               // gate preactivation exchange
__device__ __nv_bfloat16 g_hhi[2][B_ * H_];              // h bf16 hi (per step parity)
__device__ __nv_bfloat16 g_hlo[2][B_ * H_];              // h bf16 lo
__device__ __nv_bfloat16 g_ahi[(size_t)M_ * H_];
__device__ __nv_bfloat16 g_alo[(size_t)M_ * H_];
__device__ __nv_bfloat16 g_wthi[(size_t)G3_ * H_];       // Wx^T [N][K] for gemm
__device__ __nv_bfloat16 g_wtlo[(size_t)G3_ * H_];
__device__ __nv_bfloat16 g_whthi[(size_t)G3_ * H_];      // Wh^T [N][K] for scan
__device__ __nv_bfloat16 g_whtlo[(size_t)G3_ * H_];
__device__ unsigned g_grp_cnt[8];
__device__ unsigned g_root_cnt = 0;
__device__ unsigned g_bar_gen  = 0;
__device__ int g_x_is_i64 = 1;

// ---------------- helpers ----------------
__device__ __forceinline__ float fast_tanh(float x) {
    float y; asm("tanh.approx.f32 %0, %1;" : "=f"(y) : "f"(x)); return y;
}
__device__ __forceinline__ float fast_sigmoid(float x) {
    return 0.5f * fast_tanh(0.5f * x) + 0.5f;
}
__device__ __forceinline__ uint32_t smem_u32(const void* p) {
    return (uint32_t)__cvta_generic_to_shared(p);
}
__device__ __forceinline__ void cp_async16(uint32_t smem_addr, const void* gptr) {
    asm volatile("cp.async.cg.shared.global [%0], [%1], 16;"
                 :: "r"(smem_addr), "l"(gptr));
}
__device__ __forceinline__ void cp_commit() { asm volatile("cp.async.commit_group;"); }
__device__ __forceinline__ void cp_wait0() { asm volatile("cp.async.wait_group 0;"); }
__device__ __forceinline__ void cp_wait1() { asm volatile("cp.async.wait_group 1;"); }

#define LDSM_X4(r, addr) \
    asm volatile("ldmatrix.sync.aligned.m8n8.x4.shared.b16 {%0,%1,%2,%3}, [%4];" \
        : "=r"((r)[0]), "=r"((r)[1]), "=r"((r)[2]), "=r"((r)[3]) : "r"(addr))

#define MMA16816(d, a, b0, b1) \
    asm volatile("mma.sync.aligned.m16n8k16.row.col.f32.bf16.bf16.f32 " \
        "{%0,%1,%2,%3}, {%4,%5,%6,%7}, {%8,%9}, {%0,%1,%2,%3};" \
        : "+f"((d)[0]), "+f"((d)[1]), "+f"((d)[2]), "+f"((d)[3]) \
        : "r"((a)[0]), "r"((a)[1]), "r"((a)[2]), "r"((a)[3]), "r"(b0), "r"(b1))

// ---------------- int64-vs-int32 detection ----------------
__global__ void detect_kernel(const int* __restrict__ x32) {
    __shared__ int nz;
    if (threadIdx.x == 0) nz = 0;
    __syncthreads();
    if (x32[2 * threadIdx.x + 1] != 0) atomicExch(&nz, 1);
    __syncthreads();
    if (threadIdx.x == 0) g_x_is_i64 = (nz == 0) ? 1 : 0;
}

// ---------------- embedding gather (direct bf16 hi/lo) + pad mask ----------------
__global__ __launch_bounds__(128) void embed_kernel(
    const void* __restrict__ xraw, const float* __restrict__ emb,
    __nv_bfloat16* __restrict__ ahi, __nv_bfloat16* __restrict__ alo,
    float* __restrict__ mask_out)
{
    const int r = blockIdx.x;
    long long idx;
    if (g_x_is_i64) idx = ((const long long*)xraw)[r];
    else            idx = (long long)((const int*)xraw)[r];
    float4 v = ((const float4*)(emb + (size_t)idx * E_))[threadIdx.x];
    union { __nv_bfloat16 b[4]; uint2 u; } Hh, Ll;
    float f[4] = {v.x, v.y, v.z, v.w};
#pragma unroll
    for (int q = 0; q < 4; q++) {
        __nv_bfloat16 h = __float2bfloat16_rn(f[q]);
        Hh.b[q] = h;
        Ll.b[q] = __float2bfloat16_rn(f[q] - __bfloat162float(h));
    }
    ((uint2*)(ahi + (size_t)r * E_))[threadIdx.x] = Hh.u;
    ((uint2*)(alo + (size_t)r * E_))[threadIdx.x] = Ll.u;
    if (threadIdx.x == 0) mask_out[r] = (idx != 0) ? 1.0f : 0.0f;
}

// ---------------- W [K][3072] fp32 -> W^T [3072][K] bf16 hi/lo ----------------
__global__ __launch_bounds__(256) void convertWT_kernel(
    const float* __restrict__ W, __nv_bfloat16* __restrict__ Thi,
    __nv_bfloat16* __restrict__ Tlo, int K)
{
    __shared__ float t[32][33];
    const int n0 = blockIdx.x * 32, k0 = blockIdx.y * 32;
    const int tx = threadIdx.x & 31, ty = threadIdx.x >> 5;
#pragma unroll
    for (int i = 0; i < 32; i += 8)
        t[ty + i][tx] = W[(size_t)(k0 + ty + i) * G3_ + n0 + tx];
    __syncthreads();
#pragma unroll
    for (int i = 0; i < 32; i += 8) {
        float v = t[tx][ty + i];
        __nv_bfloat16 h = __float2bfloat16_rn(v);
        size_t o = (size_t)(n0 + ty + i) * K + k0 + tx;
        Thi[o] = h;
        Tlo[o] = __float2bfloat16_rn(v - __bfloat162float(h));
    }
}

// ---------------- bf16-split mma.sync GEMM (unchanged, proven) -------
#define GT_TILE   18432                // 128 * 144
#define GT_STAGE  (4 * GT_TILE)
#define GT_SMEM   (2 * GT_STAGE)       // 147456 B

__global__ __launch_bounds__(256, 1) void gemm_mma_kernel(
    const __nv_bfloat16* __restrict__ Ahi, const __nv_bfloat16* __restrict__ Alo,
    const __nv_bfloat16* __restrict__ Bhi, const __nv_bfloat16* __restrict__ Blo,
    const float* __restrict__ bias, float* __restrict__ C, int K)
{
    const uint32_t sb = smem_u32(hx_smem);
    const int tid = threadIdx.x;
    const int wid = tid >> 5, lid = tid & 31;
    const int wm = wid & 1, wn = wid >> 1;
    const int n0 = blockIdx.x * 128, m0 = blockIdx.y * 128;
    const int nch = K >> 6;

    float acc[4][4][4];
#pragma unroll
    for (int mf = 0; mf < 4; mf++)
#pragma unroll
        for (int n8 = 0; n8 < 4; n8++)
#pragma unroll
            for (int q = 0; q < 4; q++) acc[mf][n8][q] = 0.0f;

    auto stage = [&](int kc) {
        const uint32_t st = sb + (uint32_t)(kc & 1) * GT_STAGE;
        const int koff = kc * 64;
#pragma unroll
        for (int q = 0; q < 4; q++) {
            int i = tid + 256 * q;
            int row = i >> 3, seg = i & 7;
            uint32_t d = st + (uint32_t)(row * 144 + seg * 16);
            size_t ao = (size_t)(m0 + row) * K + koff + seg * 8;
            size_t bo = (size_t)(n0 + row) * K + koff + seg * 8;
            cp_async16(d,               Ahi + ao);
            cp_async16(d + GT_TILE,     Alo + ao);
            cp_async16(d + 2 * GT_TILE, Bhi + bo);
            cp_async16(d + 3 * GT_TILE, Blo + bo);
        }
        cp_commit();
    };

    const int a_row = wm * 64 + (lid & 15);
    const int a_colb = (lid >> 4) * 16;
    const int b_row = wn * 32 + ((lid >> 4) << 3) + (lid & 7);
    const int b_colb = ((lid >> 3) & 1) * 16;

    stage(0);
    for (int c = 0; c < nch; c++) {
        if (c + 1 < nch) { stage(c + 1); cp_wait1(); }
        else             { cp_wait0(); }
        __syncthreads();

        const uint32_t st = sb + (uint32_t)(c & 1) * GT_STAGE;
#pragma unroll
        for (int ks = 0; ks < 4; ks++) {
            const int kb = ks * 32;
            uint32_t ah[4][4], al[4][4], bh[2][4], bl[2][4];
#pragma unroll
            for (int mf = 0; mf < 4; mf++) {
                uint32_t addr = st + (uint32_t)((a_row + mf * 16) * 144 + kb + a_colb);
                LDSM_X4(ah[mf], addr);
                LDSM_X4(al[mf], addr + GT_TILE);
            }
#pragma unroll
            for (int nf = 0; nf < 2; nf++) {
                uint32_t addr = st + 2 * GT_TILE +
                                (uint32_t)((b_row + nf * 16) * 144 + kb + b_colb);
                LDSM_X4(bh[nf], addr);
                LDSM_X4(bl[nf], addr + GT_TILE);
            }
#pragma unroll
            for (int mf = 0; mf < 4; mf++)
#pragma unroll
                for (int n8 = 0; n8 < 4; n8++) {
                    const int nf = n8 >> 1, hh = (n8 & 1) * 2;
                    MMA16816(acc[mf][n8], ah[mf], bh[nf][hh], bh[nf][hh + 1]);
                    MMA16816(acc[mf][n8], ah[mf], bl[nf][hh], bl[nf][hh + 1]);
                    MMA16816(acc[mf][n8], al[mf], bh[nf][hh], bh[nf][hh + 1]);
                }
        }
        __syncthreads();
    }

#pragma unroll
    for (int mf = 0; mf < 4; mf++) {
        const int gm = m0 + wm * 64 + mf * 16 + (lid >> 2);
#pragma unroll
        for (int n8 = 0; n8 < 4; n8++) {
            const int gc = n0 + wn * 32 + n8 * 8 + (lid & 3) * 2;
            float2 bb = *(const float2*)(bias + gc);
            float2 v0, v1;
            v0.x = acc[mf][n8][0] + bb.x; v0.y = acc[mf][n8][1] + bb.y;
            v1.x = acc[mf][n8][2] + bb.x; v1.y = acc[mf][n8][3] + bb.y;
            *(float2*)(C + (size_t)gm * G3_ + gc)       = v0;
            *(float2*)(C + (size_t)(gm + 8) * G3_ + gc) = v1;
        }
    }
}

// ---------------- tensor-core persistent GRU scan ----------------
// 96 CTAs; CTA c owns output cols [32c, 32c+32) of the [64,3072] gate GEMM.
// Wh^T slice resident in smem (bf16 hi/lo, chunk-tiled, 272B row stride).
// h kept in global bf16 hi/lo double buffers; per step: MMA phase -> gpre,
// grid barrier, distributed GRU update, grid barrier.
#define SCN_CTAS   96
#define SCN_THREADS 256
#define SCN_N      32
#define SCN_SR     272                  // row stride bytes (128 bf16 + 16B pad)
#define SCN_ATILE  17408                // 64*272
#define SCN_APAIR  (2*SCN_ATILE)        // hi+lo
#define SCN_WCHUNK 8704                 // 32*272
#define SCN_WHI    (8*SCN_WCHUNK)       // 69632
#define SCN_ABASE  (2*SCN_WHI)          // 139264
#define SCN_SMEM   (SCN_ABASE + 2*SCN_APAIR)   // 208896

__device__ __forceinline__ void grid_barrier96(int c) {
    __syncthreads();
    if (threadIdx.x == 0) {
        __threadfence();
        unsigned gen = *(volatile unsigned*)&g_bar_gen;
        int grp = c & 7;                            // 8 groups x 12 CTAs
        if (atomicAdd(&g_grp_cnt[grp], 1u) == 11u) {
            if (atomicAdd(&g_root_cnt, 1u) == 7u) {
                atomicExch(&g_root_cnt, 0u);
#pragma unroll
                for (int i = 0; i < 8; i++) atomicExch(&g_grp_cnt[i], 0u);
                __threadfence();
                atomicAdd(&g_bar_gen, 1u);
            }
        }
        while (*(volatile unsigned*)&g_bar_gen == gen) { }
        __threadfence();
    }
    __syncthreads();
}

__global__ __launch_bounds__(SCN_THREADS, 1) void scan_mma_kernel(
    const float* __restrict__ xg,
    const __nv_bfloat16* __restrict__ wthi, const __nv_bfloat16* __restrict__ wtlo,
    const float* __restrict__ bh, float* __restrict__ hout,
    __nv_bfloat16* __restrict__ ahi, __nv_bfloat16* __restrict__ alo,
    float* __restrict__ state_out)
{
    const uint32_t sb = smem_u32(hx_smem);
    const int c = blockIdx.x, tid = threadIdx.x;
    const int wid = tid >> 5, lid = tid & 31;
    const int wm = wid & 3, wn = wid >> 2;           // 4m x 2n warp grid

    // load resident Wh^T slice (32 rows x 1024 k), chunk-tiled
#pragma unroll
    for (int q = 0; q < 16; q++) {
        int idx = tid + 256 * q;                     // 4096 slots
        int ck = idx >> 9, rest = idx & 511;
        int row = rest >> 4, seg = rest & 15;
        size_t so = (size_t)(c * SCN_N + row) * H_ + ck * 128 + seg * 8;
        uint32_t d = sb + (uint32_t)(ck * SCN_WCHUNK + row * SCN_SR + seg * 16);
        cp_async16(d,           wthi + so);
        cp_async16(d + SCN_WHI, wtlo + so);
    }
    cp_commit();
    // zero initial h state
    for (int e = c * 256 + tid; e < B_ * H_; e += SCN_CTAS * 256) {
        g_h[0][e] = 0.0f;
        g_hhi[0][e] = __float2bfloat16(0.0f);
        g_hlo[0][e] = __float2bfloat16(0.0f);
    }
    cp_wait0();
    grid_barrier96(c);

    const int a_row  = wm * 16 + (lid & 15);
    const int a_colb = (lid >> 4) * 16;
    const int b_row  = wn * 16 + ((lid >> 4) << 3) + (lid & 7);
    const int b_colb = ((lid >> 3) & 1) * 16;

    for (int t = 0; t < T_; t++) {
        const int par = t & 1, nxt = par ^ 1;
        const __nv_bfloat16* hhi = g_hhi[par];
        const __nv_bfloat16* hlo = g_hlo[par];

        auto stageA = [&](int ck) {
            uint32_t dst = sb + SCN_ABASE + (uint32_t)((ck & 1) * SCN_APAIR);
#pragma unroll
            for (int q = 0; q < 4; q++) {
                int i = tid + 256 * q;               // 1024 slots: 64 rows x 16 segs
                int row = i >> 4, seg = i & 15;
                uint32_t d = dst + (uint32_t)(row * SCN_SR + seg * 16);
                size_t so = (size_t)row * H_ + ck * 128 + seg * 8;
                cp_async16(d,             hhi + so);
                cp_async16(d + SCN_ATILE, hlo + so);
            }
            cp_commit();
        };

        stageA(0);
        float acc[2][4];
#pragma unroll
        for (int n8 = 0; n8 < 2; n8++)
#pragma unroll
            for (int q = 0; q < 4; q++) acc[n8][q] = 0.0f;

        for (int ck = 0; ck < 8; ck++) {
            if (ck + 1 < 8) { stageA(ck + 1); cp_wait1(); }
            else            { cp_wait0(); }
            __syncthreads();
            const uint32_t ab = sb + SCN_ABASE + (uint32_t)((ck & 1) * SCN_APAIR);
            const uint32_t wb = sb + (uint32_t)(ck * SCN_WCHUNK);
#pragma unroll
            for (int ks = 0; ks < 8; ks++) {
                const int kb = ks * 32;
                uint32_t ah[4], al[4], bhf[4], blf[4];
                LDSM_X4(ah,  ab + (uint32_t)(a_row * SCN_SR + kb + a_colb));
                LDSM_X4(al,  ab + SCN_ATILE + (uint32_t)(a_row * SCN_SR + kb + a_colb));
                LDSM_X4(bhf, wb + (uint32_t)(b_row * SCN_SR + kb + b_colb));
                LDSM_X4(blf, wb + SCN_WHI + (uint32_t)(b_row * SCN_SR + kb + b_colb));
#pragma unroll
                for (int n8 = 0; n8 < 2; n8++) {
                    MMA16816(acc[n8], ah, bhf[n8 * 2], bhf[n8 * 2 + 1]);
                    MMA16816(acc[n8], ah, blf[n8 * 2], blf[n8 * 2 + 1]);
                    MMA16816(acc[n8], al, bhf[n8 * 2], bhf[n8 * 2 + 1]);
                }
            }
            __syncthreads();
        }

        // write gate preactivations to exchange buffer
        {
            const int gm = wm * 16 + (lid >> 2);
#pragma unroll
            for (int n8 = 0; n8 < 2; n8++) {
                const int gc = c * SCN_N + wn * 16 + n8 * 8 + (lid & 3) * 2;
                *(float2*)&g_gpre[(size_t)gm * G3_ + gc] =
                    make_float2(acc[n8][0], acc[n8][1]);
                *(float2*)&g_gpre[(size_t)(gm + 8) * G3_ + gc] =
                    make_float2(acc[n8][2], acc[n8][3]);
            }
        }

        // prefetch phase-2 inputs (independent of gpre) before the barrier
        float pxr[3], pxz[3], pxn[3], ph[3];
#pragma unroll
        for (int k = 0; k < 3; k++) {
            int e = c * 256 + tid + k * (SCN_CTAS * 256);
            if (e < B_ * H_) {
                int b = e >> 10, j = e & 1023;
                size_t row = (size_t)b * T_ + t;
                pxr[k] = xg[row * G3_ + j];
                pxz[k] = xg[row * G3_ + H_ + j];
                pxn[k] = xg[row * G3_ + 2 * H_ + j];
                ph[k]  = g_h[par][e];
            }
        }
        grid_barrier96(c);

        // distributed GRU update
#pragma unroll
        for (int k = 0; k < 3; k++) {
            int e = c * 256 + tid + k * (SCN_CTAS * 256);
            if (e < B_ * H_) {
                int b = e >> 10, j = e & 1023;
                size_t row = (size_t)b * T_ + t;
                float gr = g_gpre[(size_t)b * G3_ + j];
                float gz = g_gpre[(size_t)b * G3_ + H_ + j];
                float gn = g_gpre[(size_t)b * G3_ + 2 * H_ + j];
                float rr = fast_sigmoid(pxr[k] + gr + bh[j]);
                float zz = fast_sigmoid(pxz[k] + gz + bh[H_ + j]);
                float nn = fast_tanh(pxn[k] + rr * (gn + bh[2 * H_ + j]));
                float hnew = (1.0f - zz) * nn + zz * ph[k];
                g_h[nxt][e] = hnew;
                hout[row * H_ + j] = hnew;
                __nv_bfloat16 hh = __float2bfloat16_rn(hnew);
                __nv_bfloat16 hl = __float2bfloat16_rn(hnew - __bfloat162float(hh));
                g_hhi[nxt][e] = hh;
                g_hlo[nxt][e] = hl;
                ahi[row * H_ + j] = hh;
                alo[row * H_ + j] = hl;
                if (t == T_ - 1) state_out[e] = hnew;
            }
        }
        grid_barrier96(c);
    }
}

// ---------------- launch ----------------
extern "C" void kernel_launch(void* const* d_in, const int* in_sizes, int n_in,
                              void* d_out, int out_size)
{
    const void*  x   = d_in[0];
    const float* emb = (const float*)d_in[1];
    const float* Wx0 = (const float*)d_in[2];
    const float* Wh0 = (const float*)d_in[3];
    const float* bx0 = (const float*)d_in[4];
    const float* bh0 = (const float*)d_in[5];
    const float* Wx  = (const float*)d_in[6];
    const float* Wh  = (const float*)d_in[7];
    const float* bx  = (const float*)d_in[8];
    const float* bh  = (const float*)d_in[9];

    float* out     = (float*)d_out;
    float* enc_out = out;
    float* states  = out + (size_t)M_ * H_;
    float* mask    = states + (size_t)4 * B_ * H_;

    void *p_xg, *p_b0, *p_ahi, *p_alo, *p_whi, *p_wlo, *p_whh, *p_whl;
    cudaGetSymbolAddress(&p_xg,  g_xg);
    cudaGetSymbolAddress(&p_b0,  g_buf0);
    cudaGetSymbolAddress(&p_ahi, g_ahi);
    cudaGetSymbolAddress(&p_alo, g_alo);
    cudaGetSymbolAddress(&p_whi, g_wthi);
    cudaGetSymbolAddress(&p_wlo, g_wtlo);
    cudaGetSymbolAddress(&p_whh, g_whthi);
    cudaGetSymbolAddress(&p_whl, g_whtlo);
    float* xg  = (float*)p_xg;
    float* b0  = (float*)p_b0;
    __nv_bfloat16* ahi = (__nv_bfloat16*)p_ahi;
    __nv_bfloat16* alo = (__nv_bfloat16*)p_alo;
    __nv_bfloat16* whi = (__nv_bfloat16*)p_whi;
    __nv_bfloat16* wlo = (__nv_bfloat16*)p_wlo;
    __nv_bfloat16* whh = (__nv_bfloat16*)p_whh;
    __nv_bfloat16* whl = (__nv_bfloat16*)p_whl;

    cudaFuncSetAttribute(scan_mma_kernel, cudaFuncAttributeMaxDynamicSharedMemorySize,
                         SCN_SMEM);
    cudaFuncSetAttribute(gemm_mma_kernel, cudaFuncAttributeMaxDynamicSharedMemorySize,
                         GT_SMEM);

    detect_kernel<<<1, 64>>>((const int*)x);
    embed_kernel<<<M_, 128>>>(x, emb, ahi, alo, mask);

    // layer 0: E=512 -> H
    convertWT_kernel<<<dim3(G3_ / 32, E_ / 32), 256>>>(Wx0, whi, wlo, E_);
    gemm_mma_kernel<<<dim3(G3_ / 128, M_ / 128), 256, GT_SMEM>>>(
        ahi, alo, whi, wlo, bx0, xg, E_);
    convertWT_kernel<<<dim3(G3_ / 32, H_ / 32), 256>>>(Wh0, whh, whl, H_);
    scan_mma_kernel<<<SCN_CTAS, SCN_THREADS, SCN_SMEM>>>(
        xg, whh, whl, bh0, b0, ahi, alo, states);

    // layers 1..3: H -> H
    for (int l = 0; l < 3; l++) {
        float* out_act = (l == 2) ? enc_out : b0;
        convertWT_kernel<<<dim3(G3_ / 32, H_ / 32), 256>>>(
            Wx + (size_t)l * H_ * G3_, whi, wlo, H_);
        gemm_mma_kernel<<<dim3(G3_ / 128, M_ / 128), 256, GT_SMEM>>>(
            ahi, alo, whi, wlo, bx + (size_t)l * G3_, xg, H_);
        convertWT_kernel<<<dim3(G3_ / 32, H_ / 32), 256>>>(
            Wh + (size_t)l * H_ * G3_, whh, whl, H_);
        scan_mma_kernel<<<SCN_CTAS, SCN_THREADS, SCN_SMEM>>>(
            xg, whh, whl, bh + (size_t)l * G3_,
            out_act, ahi, alo, states + (size_t)(l + 1) * B_ * H_);
    }
}